// round 1
// baseline (speedup 1.0000x reference)
#include <cuda_runtime.h>
#include <cmath>

// Problem constants
#define BB 16
#define NN 512
#define DD 512
#define HH 8
#define DKK 64
#define DFF 2048
#define GHH 128
#define MM (BB*NN)          // 8192
#define HC (HH*DD)          // 4096
#define CC 512              // HC / H

// ---------------- scratch (device globals; no allocation allowed) ----------
__device__ float g_qs  [MM*DD];
__device__ float g_ks  [MM*DD];
__device__ float g_vs  [MM*DD];
__device__ float g_att [MM*DD];
__device__ float g_o   [MM*DD];
__device__ float g_x   [MM*DD];
__device__ float g_ffh [MM*DFF];
__device__ float g_ff2 [MM*DD];
__device__ float g_ghr [MM*GHH];
__device__ float g_gates[MM*HH];

// ---------------- generic NT SGEMM: C = A @ W^T + bias, optional GELU ------
// A: [M,K] row-major (or, if ATRANS, A(m=b*512+n, k) = Abase[b*K*512 + k*512 + n])
// W: [Nn,K] row-major. BM=128, BN=64, BK=16, 256 threads, 8x4 microtile.
// All dims here are multiples of tile sizes (no edge guards needed).
#define BM 128
#define BN 64
#define BK 16

template<int EPI, bool ATRANS>
__global__ __launch_bounds__(256)
void gemm_nt(const float* __restrict__ A, const float* __restrict__ W,
             const float* __restrict__ bias, float* __restrict__ C,
             int M, int K, int Nn) {
    __shared__ float As[BK][BM + 4];
    __shared__ float Ws[BK][BN + 4];
    const int m0 = blockIdx.x * BM;
    const int n0 = blockIdx.y * BN;
    const int t  = threadIdx.x;
    const int tx = t & 15, ty = t >> 4;

    float acc[8][4];
#pragma unroll
    for (int i = 0; i < 8; i++)
#pragma unroll
        for (int j = 0; j < 4; j++) acc[i][j] = 0.f;

    for (int k0 = 0; k0 < K; k0 += BK) {
        if (!ATRANS) {
#pragma unroll
            for (int p = 0; p < 2; p++) {
                int row = (t >> 2) + p * 64;
                int kc  = (t & 3) * 4;
                float4 va = *(const float4*)&A[(size_t)(m0 + row) * K + k0 + kc];
                As[kc + 0][row] = va.x; As[kc + 1][row] = va.y;
                As[kc + 2][row] = va.z; As[kc + 3][row] = va.w;
            }
        } else {
            // A(m,k) = Abase[b*K*512 + k*512 + n]; block stays within one b.
            int b     = m0 >> 9;
            int nbase = m0 & 511;
#pragma unroll
            for (int p = 0; p < 2; p++) {
                int id = t + p * 256;
                int kk = id >> 5;          // 0..15
                int nv = (id & 31) * 4;    // 0..124
                float4 va = *(const float4*)&A[(size_t)b * K * 512 +
                                               (size_t)(k0 + kk) * 512 + nbase + nv];
                As[kk][nv + 0] = va.x; As[kk][nv + 1] = va.y;
                As[kk][nv + 2] = va.z; As[kk][nv + 3] = va.w;
            }
        }
        {
            int n  = t >> 2;
            int kc = (t & 3) * 4;
            float4 vw = *(const float4*)&W[(size_t)(n0 + n) * K + k0 + kc];
            Ws[kc + 0][n] = vw.x; Ws[kc + 1][n] = vw.y;
            Ws[kc + 2][n] = vw.z; Ws[kc + 3][n] = vw.w;
        }
        __syncthreads();
#pragma unroll
        for (int kk = 0; kk < BK; kk++) {
            float4 a0 = *(const float4*)&As[kk][ty * 8];
            float4 a1 = *(const float4*)&As[kk][ty * 8 + 4];
            float4 b0 = *(const float4*)&Ws[kk][tx * 4];
            float a[8] = {a0.x, a0.y, a0.z, a0.w, a1.x, a1.y, a1.z, a1.w};
            float bb[4] = {b0.x, b0.y, b0.z, b0.w};
#pragma unroll
            for (int i = 0; i < 8; i++)
#pragma unroll
                for (int j = 0; j < 4; j++) acc[i][j] += a[i] * bb[j];
        }
        __syncthreads();
    }
#pragma unroll
    for (int i = 0; i < 8; i++) {
        int row = m0 + ty * 8 + i;
        int col = n0 + tx * 4;
        float4 r;
        float* pr = &r.x;
#pragma unroll
        for (int j = 0; j < 4; j++) {
            float vv = acc[i][j] + bias[col + j];
            if (EPI == 1) vv = 0.5f * vv * (1.f + erff(vv * 0.70710678118654752f));
            pr[j] = vv;
        }
        *(float4*)&C[(size_t)row * Nn + col] = r;
    }
}

// ---------------- attention: per (b,h), 64 q-rows per block ----------------
// scores tile [64][512] lives in smem; two passes (K then V); exact softmax.
#define ATT_SROW 516  // padded row of Ss
#define ATT_SMEM ((64*ATT_SROW + 2*64*68 + 64) * 4)

__global__ __launch_bounds__(256)
void attn_kernel(const float* __restrict__ Q, const float* __restrict__ Kk,
                 const float* __restrict__ V, float* __restrict__ O) {
    extern __shared__ float sm[];
    float* Ss  = sm;                    // [64][516]
    float* Qt  = sm + 64 * ATT_SROW;    // [64 d][68 r]
    float* KVt = Qt + 64 * 68;          // [64][68] (transposed K, then V rows)
    float* inv = KVt + 64 * 68;         // [64]

    const int bh = blockIdx.x;
    const int b = bh >> 3, h = bh & 7;
    const int q0 = blockIdx.y * 64;
    const int t  = threadIdx.x;
    const int tx = t & 15, ty = t >> 4;
    const size_t base = ((size_t)b * NN) * DD + h * DKK;  // + n*512 + d
    const float scale = 0.125f;  // DK^-0.5

    // load Q tile transposed: Qt[d][r]
#pragma unroll
    for (int p = 0; p < 4; p++) {
        int r = (t >> 4) + p * 16;
        int d = (t & 15) * 4;
        float4 vq = *(const float4*)&Q[base + (size_t)(q0 + r) * DD + d];
        Qt[(d + 0) * 68 + r] = vq.x; Qt[(d + 1) * 68 + r] = vq.y;
        Qt[(d + 2) * 68 + r] = vq.z; Qt[(d + 3) * 68 + r] = vq.w;
    }

    // pass 1: scores
    for (int c0 = 0; c0 < NN; c0 += 64) {
#pragma unroll
        for (int p = 0; p < 4; p++) {
            int r = (t >> 4) + p * 16;
            int d = (t & 15) * 4;
            float4 vk = *(const float4*)&Kk[base + (size_t)(c0 + r) * DD + d];
            KVt[(d + 0) * 68 + r] = vk.x; KVt[(d + 1) * 68 + r] = vk.y;
            KVt[(d + 2) * 68 + r] = vk.z; KVt[(d + 3) * 68 + r] = vk.w;
        }
        __syncthreads();
        float s[4][4];
#pragma unroll
        for (int i = 0; i < 4; i++)
#pragma unroll
            for (int j = 0; j < 4; j++) s[i][j] = 0.f;
#pragma unroll 8
        for (int d = 0; d < 64; d++) {
            float4 a = *(const float4*)&Qt[d * 68 + ty * 4];
            float4 bq = *(const float4*)&KVt[d * 68 + tx * 4];
            float av[4] = {a.x, a.y, a.z, a.w};
            float bv[4] = {bq.x, bq.y, bq.z, bq.w};
#pragma unroll
            for (int i = 0; i < 4; i++)
#pragma unroll
                for (int j = 0; j < 4; j++) s[i][j] += av[i] * bv[j];
        }
#pragma unroll
        for (int i = 0; i < 4; i++)
#pragma unroll
            for (int j = 0; j < 4; j++)
                Ss[(ty * 4 + i) * ATT_SROW + c0 + tx * 4 + j] = s[i][j] * scale;
        __syncthreads();
    }

    // softmax (unnormalized exp + reciprocal row sum)
    {
        int row = t >> 2;     // 0..63
        int qd  = t & 3;      // quarter of the 512 keys
        float* prow = &Ss[row * ATT_SROW + qd * 128];
        float mx = -1e30f;
#pragma unroll 8
        for (int i = 0; i < 128; i++) mx = fmaxf(mx, prow[i]);
        mx = fmaxf(mx, __shfl_xor_sync(0xFFFFFFFFu, mx, 1));
        mx = fmaxf(mx, __shfl_xor_sync(0xFFFFFFFFu, mx, 2));
        float sum = 0.f;
#pragma unroll 8
        for (int i = 0; i < 128; i++) {
            float e = __expf(prow[i] - mx);
            prow[i] = e;
            sum += e;
        }
        sum += __shfl_xor_sync(0xFFFFFFFFu, sum, 1);
        sum += __shfl_xor_sync(0xFFFFFFFFu, sum, 2);
        if (qd == 0) inv[row] = 1.f / sum;
    }
    __syncthreads();

    // pass 2: O = P @ V
    float o[4][4];
#pragma unroll
    for (int i = 0; i < 4; i++)
#pragma unroll
        for (int j = 0; j < 4; j++) o[i][j] = 0.f;
    for (int c0 = 0; c0 < NN; c0 += 64) {
#pragma unroll
        for (int p = 0; p < 4; p++) {
            int r = (t >> 4) + p * 16;
            int d = (t & 15) * 4;
            float4 vv = *(const float4*)&V[base + (size_t)(c0 + r) * DD + d];
            *(float4*)&KVt[r * 68 + d] = vv;
        }
        __syncthreads();
#pragma unroll 4
        for (int kk = 0; kk < 64; kk++) {
            float4 vv = *(const float4*)&KVt[kk * 68 + tx * 4];
            float vvv[4] = {vv.x, vv.y, vv.z, vv.w};
            float pp[4];
#pragma unroll
            for (int i = 0; i < 4; i++)
                pp[i] = Ss[(ty * 4 + i) * ATT_SROW + c0 + kk];
#pragma unroll
            for (int i = 0; i < 4; i++)
#pragma unroll
                for (int j = 0; j < 4; j++) o[i][j] += pp[i] * vvv[j];
        }
        __syncthreads();
    }
#pragma unroll
    for (int i = 0; i < 4; i++) {
        float iv = inv[ty * 4 + i];
        float4 r = {o[i][0] * iv, o[i][1] * iv, o[i][2] * iv, o[i][3] * iv};
        *(float4*)&O[base + (size_t)(q0 + ty * 4 + i) * DD + tx * 4] = r;
    }
}

// ---------------- residual + LayerNorm over D=512 --------------------------
__global__ __launch_bounds__(128)
void add_ln_kernel(const float* __restrict__ X, const float* __restrict__ Y,
                   const float* __restrict__ g, const float* __restrict__ bt,
                   float* __restrict__ out) {
    __shared__ float sh[8];
    const int row = blockIdx.x;
    const int t = threadIdx.x;
    float4 x4 = *(const float4*)&X[(size_t)row * 512 + t * 4];
    float4 y4 = *(const float4*)&Y[(size_t)row * 512 + t * 4];
    float v[4] = {x4.x + y4.x, x4.y + y4.y, x4.z + y4.z, x4.w + y4.w};
    float s = v[0] + v[1] + v[2] + v[3];
    float s2 = v[0]*v[0] + v[1]*v[1] + v[2]*v[2] + v[3]*v[3];
#pragma unroll
    for (int off = 16; off; off >>= 1) {
        s  += __shfl_xor_sync(0xFFFFFFFFu, s, off);
        s2 += __shfl_xor_sync(0xFFFFFFFFu, s2, off);
    }
    if ((t & 31) == 0) { sh[t >> 5] = s; sh[4 + (t >> 5)] = s2; }
    __syncthreads();
    s  = sh[0] + sh[1] + sh[2] + sh[3];
    s2 = sh[4] + sh[5] + sh[6] + sh[7];
    float mean = s * (1.f / 512.f);
    float var  = s2 * (1.f / 512.f) - mean * mean;
    float rs = rsqrtf(var + 1e-5f);
    float4 g4 = *(const float4*)&g[t * 4];
    float4 b4 = *(const float4*)&bt[t * 4];
    float4 r;
    r.x = (v[0] - mean) * rs * g4.x + b4.x;
    r.y = (v[1] - mean) * rs * g4.y + b4.y;
    r.z = (v[2] - mean) * rs * g4.z + b4.z;
    r.w = (v[3] - mean) * rs * g4.w + b4.w;
    *(float4*)&out[(size_t)row * 512 + t * 4] = r;
}

// ---------------- gate finisher: LN(128) -> ReLU -> Linear(128,8) -> softmax
__global__ __launch_bounds__(128)
void gate_finish_kernel(const float* __restrict__ Hraw,
                        const float* __restrict__ lng, const float* __restrict__ lnb,
                        const float* __restrict__ Wg2, const float* __restrict__ bg2,
                        float* __restrict__ gates) {
    __shared__ float sh[8];
    __shared__ float sv[128];
    __shared__ float logits[8];
    const int row = blockIdx.x;
    const int t = threadIdx.x;
    float v = Hraw[(size_t)row * 128 + t];
    float s = v, s2 = v * v;
#pragma unroll
    for (int off = 16; off; off >>= 1) {
        s  += __shfl_xor_sync(0xFFFFFFFFu, s, off);
        s2 += __shfl_xor_sync(0xFFFFFFFFu, s2, off);
    }
    if ((t & 31) == 0) { sh[t >> 5] = s; sh[4 + (t >> 5)] = s2; }
    __syncthreads();
    s  = sh[0] + sh[1] + sh[2] + sh[3];
    s2 = sh[4] + sh[5] + sh[6] + sh[7];
    float mean = s * (1.f / 128.f);
    float var  = s2 * (1.f / 128.f) - mean * mean;
    float x = (v - mean) * rsqrtf(var + 1e-5f) * lng[t] + lnb[t];
    sv[t] = fmaxf(x, 0.f);
    __syncthreads();
    int w = t >> 5, lane = t & 31;
    for (int hh = w; hh < 8; hh += 4) {
        const float* wr = &Wg2[hh * 128];
        float p = sv[lane] * wr[lane] + sv[lane + 32] * wr[lane + 32]
                + sv[lane + 64] * wr[lane + 64] + sv[lane + 96] * wr[lane + 96];
#pragma unroll
        for (int off = 16; off; off >>= 1) p += __shfl_xor_sync(0xFFFFFFFFu, p, off);
        if (lane == 0) logits[hh] = p + bg2[hh];
    }
    __syncthreads();
    if (t == 0) {
        float mx = -1e30f;
#pragma unroll
        for (int hh = 0; hh < 8; hh++) mx = fmaxf(mx, logits[hh]);
        float e[8], sum = 0.f;
#pragma unroll
        for (int hh = 0; hh < 8; hh++) { e[hh] = __expf(logits[hh] - mx); sum += e[hh]; }
        float isum = 1.f / sum;
#pragma unroll
        for (int hh = 0; hh < 8; hh++) gates[(size_t)row * 8 + hh] = e[hh] * isum;
    }
}

// ---------------- fused = sum_h cma[b, h*C + c, n] * gates[b,n,h] ----------
__global__ __launch_bounds__(256)
void fused_kernel(const float* __restrict__ cma, const float* __restrict__ gates,
                  float* __restrict__ out) {
    int idx = blockIdx.x * 256 + threadIdx.x;   // over B*C*N = 4194304
    int n = idx & 511;
    int c = (idx >> 9) & 511;
    int b = idx >> 18;
    const float* gp = &gates[((size_t)b * 512 + n) * 8];
    const float* cp = &cma[(size_t)b * HC * NN + (size_t)c * NN + n];
    float acc = 0.f;
#pragma unroll
    for (int hh = 0; hh < 8; hh++)
        acc += cp[(size_t)hh * CC * NN] * gp[hh];
    out[idx] = acc;
}

// ---------------- host launcher --------------------------------------------
extern "C" void kernel_launch(void* const* d_in, const int* in_sizes, int n_in,
                              void* d_out, int out_size) {
    const float* q    = (const float*)d_in[0];
    const float* k    = (const float*)d_in[1];
    const float* v    = (const float*)d_in[2];
    const float* cma  = (const float*)d_in[3];
    const float* Wq   = (const float*)d_in[4];
    const float* bq   = (const float*)d_in[5];
    const float* Wk   = (const float*)d_in[6];
    const float* bk   = (const float*)d_in[7];
    const float* Wv   = (const float*)d_in[8];
    const float* bv   = (const float*)d_in[9];
    const float* Wo   = (const float*)d_in[10];
    const float* bo   = (const float*)d_in[11];
    const float* ln1g = (const float*)d_in[12];
    const float* ln1b = (const float*)d_in[13];
    const float* ln2g = (const float*)d_in[14];
    const float* ln2b = (const float*)d_in[15];
    const float* W1   = (const float*)d_in[16];
    const float* b1   = (const float*)d_in[17];
    const float* W2   = (const float*)d_in[18];
    const float* b2   = (const float*)d_in[19];
    const float* Wg1  = (const float*)d_in[20];
    const float* bg1  = (const float*)d_in[21];
    const float* lngg = (const float*)d_in[22];
    const float* lngb = (const float*)d_in[23];
    const float* Wg2  = (const float*)d_in[24];
    const float* bg2  = (const float*)d_in[25];

    float *p_qs, *p_ks, *p_vs, *p_att, *p_o, *p_x, *p_ffh, *p_ff2, *p_ghr, *p_gates;
    cudaGetSymbolAddress((void**)&p_qs,  g_qs);
    cudaGetSymbolAddress((void**)&p_ks,  g_ks);
    cudaGetSymbolAddress((void**)&p_vs,  g_vs);
    cudaGetSymbolAddress((void**)&p_att, g_att);
    cudaGetSymbolAddress((void**)&p_o,   g_o);
    cudaGetSymbolAddress((void**)&p_x,   g_x);
    cudaGetSymbolAddress((void**)&p_ffh, g_ffh);
    cudaGetSymbolAddress((void**)&p_ff2, g_ff2);
    cudaGetSymbolAddress((void**)&p_ghr, g_ghr);
    cudaGetSymbolAddress((void**)&p_gates, g_gates);

    cudaFuncSetAttribute(attn_kernel, cudaFuncAttributeMaxDynamicSharedMemorySize, ATT_SMEM);

    float* out_enc   = (float*)d_out;                       // [B,N,D]
    float* out_fused = (float*)d_out + (size_t)MM * DD;     // [B,C,N]

    // QKV projections
    gemm_nt<0,false><<<dim3(MM/BM, DD/BN), 256>>>(q, Wq, bq, p_qs, MM, DD, DD);
    gemm_nt<0,false><<<dim3(MM/BM, DD/BN), 256>>>(k, Wk, bk, p_ks, MM, DD, DD);
    gemm_nt<0,false><<<dim3(MM/BM, DD/BN), 256>>>(v, Wv, bv, p_vs, MM, DD, DD);
    // attention
    attn_kernel<<<dim3(BB*HH, NN/64), 256, ATT_SMEM>>>(p_qs, p_ks, p_vs, p_att);
    // output projection + LN1
    gemm_nt<0,false><<<dim3(MM/BM, DD/BN), 256>>>(p_att, Wo, bo, p_o, MM, DD, DD);
    add_ln_kernel<<<MM, 128>>>(q, p_o, ln1g, ln1b, p_x);
    // FFN
    gemm_nt<1,false><<<dim3(MM/BM, DFF/BN), 256>>>(p_x, W1, b1, p_ffh, MM, DD, DFF);
    gemm_nt<0,false><<<dim3(MM/BM, DD/BN), 256>>>(p_ffh, W2, b2, p_ff2, MM, DFF, DD);
    add_ln_kernel<<<MM, 128>>>(p_x, p_ff2, ln2g, ln2b, out_enc);
    // gate MLP (A read strided straight out of cma) + finisher
    gemm_nt<0,true><<<dim3(MM/BM, GHH/BN), 256>>>(cma, Wg1, bg1, p_ghr, MM, HC, GHH);
    gate_finish_kernel<<<MM, 128>>>(p_ghr, lngg, lngb, Wg2, bg2, p_gates);
    // gated fusion
    fused_kernel<<<(BB*CC*NN)/256, 256>>>(cma, p_gates, out_fused);
}

// round 3
// speedup vs baseline: 1.6069x; 1.6069x over previous
#include <cuda_runtime.h>
#include <cstdint>
#include <cmath>

// Problem constants
#define BB 16
#define NN 512
#define DD 512
#define HH 8
#define DKK 64
#define DFF 2048
#define GHH 128
#define MM (BB*NN)          // 8192
#define HC (HH*DD)          // 4096
#define CC 512              // HC / H

// ---------------- scratch (device globals; no allocation allowed) ----------
__device__ float g_qs  [MM*DD];
__device__ float g_ks  [MM*DD];
__device__ float g_vs  [MM*DD];
__device__ float g_att [MM*DD];
__device__ float g_o   [MM*DD];
__device__ float g_x   [MM*DD];
__device__ float g_ffh [MM*DFF];
__device__ float g_ff2 [MM*DD];
__device__ float g_ghr [MM*GHH];
__device__ float g_gates[MM*HH];

__device__ __forceinline__ uint32_t f2tf32(float x) {
    uint32_t r;
    asm("cvt.rna.tf32.f32 %0, %1;" : "=r"(r) : "f"(x));
    return r;
}

// ================= tf32 mma.sync GEMM: C = A @ W^T + bias =================
// CTA tile 128x128, BK=32. 256 threads = 8 warps (4 M x 2 N), warp tile 32x64.
// mma.m16n8k8 tf32, fp32 accum. EPI=1 -> exact GELU.
// ATRANS: A(m=b*512+n, k) = Abase[b*K*512 + k*512 + n]  (gate GEMM on cma)
template<int EPI, bool ATRANS>
__global__ __launch_bounds__(256)
void gemm_mma(const float* __restrict__ A, const float* __restrict__ W,
              const float* __restrict__ bias, float* __restrict__ C,
              int M, int K, int Nn) {
    __shared__ uint32_t As[32][132];   // [k][m]
    __shared__ uint32_t Bs[32][132];   // [k][n]
    const int t = threadIdx.x;
    const int lane = t & 31, wid = t >> 5;
    const int wm = (wid >> 1) * 32;    // warp M offset in tile
    const int wn = (wid & 1) * 64;     // warp N offset in tile
    const int m0 = blockIdx.x * 128, n0 = blockIdx.y * 128;
    const int g = lane >> 2, c = lane & 3;

    float acc[2][8][4];
#pragma unroll
    for (int im = 0; im < 2; im++)
#pragma unroll
        for (int jn = 0; jn < 8; jn++)
#pragma unroll
            for (int e = 0; e < 4; e++) acc[im][jn][e] = 0.f;

    for (int k0 = 0; k0 < K; k0 += 32) {
        // ---- A tile -> As[k][m] ----
        if (!ATRANS) {
#pragma unroll
            for (int p = 0; p < 4; p++) {
                int idx = p * 256 + t;
                int row = idx >> 3, f4 = (idx & 7) * 4;
                float4 v = *(const float4*)&A[(size_t)(m0 + row) * K + k0 + f4];
                As[f4 + 0][row] = f2tf32(v.x);
                As[f4 + 1][row] = f2tf32(v.y);
                As[f4 + 2][row] = f2tf32(v.z);
                As[f4 + 3][row] = f2tf32(v.w);
            }
        } else {
            const int b = m0 >> 9, nb = m0 & 511;
#pragma unroll
            for (int p = 0; p < 4; p++) {
                int idx = p * 256 + t;
                int kc = idx >> 5, nf = (idx & 31) * 4;
                float4 v = *(const float4*)&A[(size_t)b * K * 512 +
                                              (size_t)(k0 + kc) * 512 + nb + nf];
                uint4 u = {f2tf32(v.x), f2tf32(v.y), f2tf32(v.z), f2tf32(v.w)};
                *(uint4*)&As[kc][nf] = u;
            }
        }
        // ---- B tile: Bs[k][n] = W[n0+n][k0+k] ----
#pragma unroll
        for (int p = 0; p < 4; p++) {
            int idx = p * 256 + t;
            int row = idx >> 3, f4 = (idx & 7) * 4;
            float4 v = *(const float4*)&W[(size_t)(n0 + row) * K + k0 + f4];
            Bs[f4 + 0][row] = f2tf32(v.x);
            Bs[f4 + 1][row] = f2tf32(v.y);
            Bs[f4 + 2][row] = f2tf32(v.z);
            Bs[f4 + 3][row] = f2tf32(v.w);
        }
        __syncthreads();
#pragma unroll
        for (int ks = 0; ks < 32; ks += 8) {
            uint32_t af[2][4];
#pragma unroll
            for (int im = 0; im < 2; im++) {
                int m = wm + im * 16;
                af[im][0] = As[ks + c][m + g];
                af[im][1] = As[ks + c][m + g + 8];
                af[im][2] = As[ks + c + 4][m + g];
                af[im][3] = As[ks + c + 4][m + g + 8];
            }
#pragma unroll
            for (int jn = 0; jn < 8; jn++) {
                int n = wn + jn * 8;
                uint32_t b0 = Bs[ks + c][n + g];
                uint32_t b1 = Bs[ks + c + 4][n + g];
#pragma unroll
                for (int im = 0; im < 2; im++) {
                    asm volatile(
                        "mma.sync.aligned.m16n8k8.row.col.f32.tf32.tf32.f32 "
                        "{%0,%1,%2,%3}, {%4,%5,%6,%7}, {%8,%9}, {%0,%1,%2,%3};"
                        : "+f"(acc[im][jn][0]), "+f"(acc[im][jn][1]),
                          "+f"(acc[im][jn][2]), "+f"(acc[im][jn][3])
                        : "r"(af[im][0]), "r"(af[im][1]),
                          "r"(af[im][2]), "r"(af[im][3]),
                          "r"(b0), "r"(b1));
                }
            }
        }
        __syncthreads();
    }
    // ---- epilogue ----
#pragma unroll
    for (int jn = 0; jn < 8; jn++) {
        int col = n0 + wn + jn * 8 + 2 * c;
        float bv0 = bias[col], bv1 = bias[col + 1];
#pragma unroll
        for (int im = 0; im < 2; im++) {
            int row = m0 + wm + im * 16 + g;
            float v00 = acc[im][jn][0] + bv0;
            float v01 = acc[im][jn][1] + bv1;
            float v10 = acc[im][jn][2] + bv0;
            float v11 = acc[im][jn][3] + bv1;
            if (EPI == 1) {
                v00 = 0.5f * v00 * (1.f + erff(v00 * 0.70710678118654752f));
                v01 = 0.5f * v01 * (1.f + erff(v01 * 0.70710678118654752f));
                v10 = 0.5f * v10 * (1.f + erff(v10 * 0.70710678118654752f));
                v11 = 0.5f * v11 * (1.f + erff(v11 * 0.70710678118654752f));
            }
            float2 r0 = {v00, v01}, r1 = {v10, v11};
            *(float2*)&C[(size_t)row * Nn + col] = r0;
            *(float2*)&C[(size_t)(row + 8) * Nn + col] = r1;
        }
    }
}

// ---------------- attention: per (b,h), 64 q-rows per block ----------------
#define ATT_SROW 516
#define ATT_SMEM ((64*ATT_SROW + 2*64*68 + 64) * 4)

__global__ __launch_bounds__(256)
void attn_kernel(const float* __restrict__ Q, const float* __restrict__ Kk,
                 const float* __restrict__ V, float* __restrict__ O) {
    extern __shared__ float sm[];
    float* Ss  = sm;
    float* Qt  = sm + 64 * ATT_SROW;
    float* KVt = Qt + 64 * 68;
    float* inv = KVt + 64 * 68;

    const int bh = blockIdx.x;
    const int b = bh >> 3, h = bh & 7;
    const int q0 = blockIdx.y * 64;
    const int t  = threadIdx.x;
    const int tx = t & 15, ty = t >> 4;
    const size_t base = ((size_t)b * NN) * DD + h * DKK;
    const float scale = 0.125f;

#pragma unroll
    for (int p = 0; p < 4; p++) {
        int r = (t >> 4) + p * 16;
        int d = (t & 15) * 4;
        float4 vq = *(const float4*)&Q[base + (size_t)(q0 + r) * DD + d];
        Qt[(d + 0) * 68 + r] = vq.x; Qt[(d + 1) * 68 + r] = vq.y;
        Qt[(d + 2) * 68 + r] = vq.z; Qt[(d + 3) * 68 + r] = vq.w;
    }

    for (int c0 = 0; c0 < NN; c0 += 64) {
#pragma unroll
        for (int p = 0; p < 4; p++) {
            int r = (t >> 4) + p * 16;
            int d = (t & 15) * 4;
            float4 vk = *(const float4*)&Kk[base + (size_t)(c0 + r) * DD + d];
            KVt[(d + 0) * 68 + r] = vk.x; KVt[(d + 1) * 68 + r] = vk.y;
            KVt[(d + 2) * 68 + r] = vk.z; KVt[(d + 3) * 68 + r] = vk.w;
        }
        __syncthreads();
        float s[4][4];
#pragma unroll
        for (int i = 0; i < 4; i++)
#pragma unroll
            for (int j = 0; j < 4; j++) s[i][j] = 0.f;
#pragma unroll 8
        for (int d = 0; d < 64; d++) {
            float4 a = *(const float4*)&Qt[d * 68 + ty * 4];
            float4 bq = *(const float4*)&KVt[d * 68 + tx * 4];
            float av[4] = {a.x, a.y, a.z, a.w};
            float bv[4] = {bq.x, bq.y, bq.z, bq.w};
#pragma unroll
            for (int i = 0; i < 4; i++)
#pragma unroll
                for (int j = 0; j < 4; j++) s[i][j] += av[i] * bv[j];
        }
#pragma unroll
        for (int i = 0; i < 4; i++)
#pragma unroll
            for (int j = 0; j < 4; j++)
                Ss[(ty * 4 + i) * ATT_SROW + c0 + tx * 4 + j] = s[i][j] * scale;
        __syncthreads();
    }

    {
        int row = t >> 2;
        int qd  = t & 3;
        float* prow = &Ss[row * ATT_SROW + qd * 128];
        float mx = -1e30f;
#pragma unroll 8
        for (int i = 0; i < 128; i++) mx = fmaxf(mx, prow[i]);
        mx = fmaxf(mx, __shfl_xor_sync(0xFFFFFFFFu, mx, 1));
        mx = fmaxf(mx, __shfl_xor_sync(0xFFFFFFFFu, mx, 2));
        float sum = 0.f;
#pragma unroll 8
        for (int i = 0; i < 128; i++) {
            float e = __expf(prow[i] - mx);
            prow[i] = e;
            sum += e;
        }
        sum += __shfl_xor_sync(0xFFFFFFFFu, sum, 1);
        sum += __shfl_xor_sync(0xFFFFFFFFu, sum, 2);
        if (qd == 0) inv[row] = 1.f / sum;
    }
    __syncthreads();

    float o[4][4];
#pragma unroll
    for (int i = 0; i < 4; i++)
#pragma unroll
        for (int j = 0; j < 4; j++) o[i][j] = 0.f;
    for (int c0 = 0; c0 < NN; c0 += 64) {
#pragma unroll
        for (int p = 0; p < 4; p++) {
            int r = (t >> 4) + p * 16;
            int d = (t & 15) * 4;
            float4 vv = *(const float4*)&V[base + (size_t)(c0 + r) * DD + d];
            *(float4*)&KVt[r * 68 + d] = vv;
        }
        __syncthreads();
#pragma unroll 4
        for (int kk = 0; kk < 64; kk++) {
            float4 vv = *(const float4*)&KVt[kk * 68 + tx * 4];
            float vvv[4] = {vv.x, vv.y, vv.z, vv.w};
            float pp[4];
#pragma unroll
            for (int i = 0; i < 4; i++)
                pp[i] = Ss[(ty * 4 + i) * ATT_SROW + c0 + kk];
#pragma unroll
            for (int i = 0; i < 4; i++)
#pragma unroll
                for (int j = 0; j < 4; j++) o[i][j] += pp[i] * vvv[j];
        }
        __syncthreads();
    }
#pragma unroll
    for (int i = 0; i < 4; i++) {
        float iv = inv[ty * 4 + i];
        float4 r = {o[i][0] * iv, o[i][1] * iv, o[i][2] * iv, o[i][3] * iv};
        *(float4*)&O[base + (size_t)(q0 + ty * 4 + i) * DD + tx * 4] = r;
    }
}

// ---------------- residual + LayerNorm over D=512 --------------------------
__global__ __launch_bounds__(128)
void add_ln_kernel(const float* __restrict__ X, const float* __restrict__ Y,
                   const float* __restrict__ g, const float* __restrict__ bt,
                   float* __restrict__ out) {
    __shared__ float sh[8];
    const int row = blockIdx.x;
    const int t = threadIdx.x;
    float4 x4 = *(const float4*)&X[(size_t)row * 512 + t * 4];
    float4 y4 = *(const float4*)&Y[(size_t)row * 512 + t * 4];
    float v[4] = {x4.x + y4.x, x4.y + y4.y, x4.z + y4.z, x4.w + y4.w};
    float s = v[0] + v[1] + v[2] + v[3];
    float s2 = v[0]*v[0] + v[1]*v[1] + v[2]*v[2] + v[3]*v[3];
#pragma unroll
    for (int off = 16; off; off >>= 1) {
        s  += __shfl_xor_sync(0xFFFFFFFFu, s, off);
        s2 += __shfl_xor_sync(0xFFFFFFFFu, s2, off);
    }
    if ((t & 31) == 0) { sh[t >> 5] = s; sh[4 + (t >> 5)] = s2; }
    __syncthreads();
    s  = sh[0] + sh[1] + sh[2] + sh[3];
    s2 = sh[4] + sh[5] + sh[6] + sh[7];
    float mean = s * (1.f / 512.f);
    float var  = s2 * (1.f / 512.f) - mean * mean;
    float rs = rsqrtf(var + 1e-5f);
    float4 g4 = *(const float4*)&g[t * 4];
    float4 b4 = *(const float4*)&bt[t * 4];
    float4 r;
    r.x = (v[0] - mean) * rs * g4.x + b4.x;
    r.y = (v[1] - mean) * rs * g4.y + b4.y;
    r.z = (v[2] - mean) * rs * g4.z + b4.z;
    r.w = (v[3] - mean) * rs * g4.w + b4.w;
    *(float4*)&out[(size_t)row * 512 + t * 4] = r;
}

// ---------------- gate finisher: LN(128) -> ReLU -> Linear(128,8) -> softmax
__global__ __launch_bounds__(128)
void gate_finish_kernel(const float* __restrict__ Hraw,
                        const float* __restrict__ lng, const float* __restrict__ lnb,
                        const float* __restrict__ Wg2, const float* __restrict__ bg2,
                        float* __restrict__ gates) {
    __shared__ float sh[8];
    __shared__ float sv[128];
    __shared__ float logits[8];
    const int row = blockIdx.x;
    const int t = threadIdx.x;
    float v = Hraw[(size_t)row * 128 + t];
    float s = v, s2 = v * v;
#pragma unroll
    for (int off = 16; off; off >>= 1) {
        s  += __shfl_xor_sync(0xFFFFFFFFu, s, off);
        s2 += __shfl_xor_sync(0xFFFFFFFFu, s2, off);
    }
    if ((t & 31) == 0) { sh[t >> 5] = s; sh[4 + (t >> 5)] = s2; }
    __syncthreads();
    s  = sh[0] + sh[1] + sh[2] + sh[3];
    s2 = sh[4] + sh[5] + sh[6] + sh[7];
    float mean = s * (1.f / 128.f);
    float var  = s2 * (1.f / 128.f) - mean * mean;
    float x = (v - mean) * rsqrtf(var + 1e-5f) * lng[t] + lnb[t];
    sv[t] = fmaxf(x, 0.f);
    __syncthreads();
    int w = t >> 5, lane = t & 31;
    for (int hh = w; hh < 8; hh += 4) {
        const float* wr = &Wg2[hh * 128];
        float p = sv[lane] * wr[lane] + sv[lane + 32] * wr[lane + 32]
                + sv[lane + 64] * wr[lane + 64] + sv[lane + 96] * wr[lane + 96];
#pragma unroll
        for (int off = 16; off; off >>= 1) p += __shfl_xor_sync(0xFFFFFFFFu, p, off);
        if (lane == 0) logits[hh] = p + bg2[hh];
    }
    __syncthreads();
    if (t == 0) {
        float mx = -1e30f;
#pragma unroll
        for (int hh = 0; hh < 8; hh++) mx = fmaxf(mx, logits[hh]);
        float e[8], sum = 0.f;
#pragma unroll
        for (int hh = 0; hh < 8; hh++) { e[hh] = __expf(logits[hh] - mx); sum += e[hh]; }
        float isum = 1.f / sum;
#pragma unroll
        for (int hh = 0; hh < 8; hh++) gates[(size_t)row * 8 + hh] = e[hh] * isum;
    }
}

// ---------------- fused = sum_h cma[b, h*C + c, n] * gates[b,n,h] ----------
__global__ __launch_bounds__(256)
void fused_kernel(const float* __restrict__ cma, const float* __restrict__ gates,
                  float* __restrict__ out) {
    int idx = blockIdx.x * 256 + threadIdx.x;
    int n = idx & 511;
    int c = (idx >> 9) & 511;
    int b = idx >> 18;
    const float* gp = &gates[((size_t)b * 512 + n) * 8];
    const float* cp = &cma[(size_t)b * HC * NN + (size_t)c * NN + n];
    float acc = 0.f;
#pragma unroll
    for (int hh = 0; hh < 8; hh++)
        acc += cp[(size_t)hh * CC * NN] * gp[hh];
    out[idx] = acc;
}

// ---------------- host launcher --------------------------------------------
extern "C" void kernel_launch(void* const* d_in, const int* in_sizes, int n_in,
                              void* d_out, int out_size) {
    const float* q    = (const float*)d_in[0];
    const float* k    = (const float*)d_in[1];
    const float* v    = (const float*)d_in[2];
    const float* cma  = (const float*)d_in[3];
    const float* Wq   = (const float*)d_in[4];
    const float* bq   = (const float*)d_in[5];
    const float* Wk   = (const float*)d_in[6];
    const float* bk   = (const float*)d_in[7];
    const float* Wv   = (const float*)d_in[8];
    const float* bv   = (const float*)d_in[9];
    const float* Wo   = (const float*)d_in[10];
    const float* bo   = (const float*)d_in[11];
    const float* ln1g = (const float*)d_in[12];
    const float* ln1b = (const float*)d_in[13];
    const float* ln2g = (const float*)d_in[14];
    const float* ln2b = (const float*)d_in[15];
    const float* W1   = (const float*)d_in[16];
    const float* b1   = (const float*)d_in[17];
    const float* W2   = (const float*)d_in[18];
    const float* b2   = (const float*)d_in[19];
    const float* Wg1  = (const float*)d_in[20];
    const float* bg1  = (const float*)d_in[21];
    const float* lngg = (const float*)d_in[22];
    const float* lngb = (const float*)d_in[23];
    const float* Wg2  = (const float*)d_in[24];
    const float* bg2  = (const float*)d_in[25];

    float *p_qs, *p_ks, *p_vs, *p_att, *p_o, *p_x, *p_ffh, *p_ff2, *p_ghr, *p_gates;
    cudaGetSymbolAddress((void**)&p_qs,  g_qs);
    cudaGetSymbolAddress((void**)&p_ks,  g_ks);
    cudaGetSymbolAddress((void**)&p_vs,  g_vs);
    cudaGetSymbolAddress((void**)&p_att, g_att);
    cudaGetSymbolAddress((void**)&p_o,   g_o);
    cudaGetSymbolAddress((void**)&p_x,   g_x);
    cudaGetSymbolAddress((void**)&p_ffh, g_ffh);
    cudaGetSymbolAddress((void**)&p_ff2, g_ff2);
    cudaGetSymbolAddress((void**)&p_ghr, g_ghr);
    cudaGetSymbolAddress((void**)&p_gates, g_gates);

    cudaFuncSetAttribute(attn_kernel, cudaFuncAttributeMaxDynamicSharedMemorySize, ATT_SMEM);

    float* out_enc   = (float*)d_out;                       // [B,N,D]
    float* out_fused = (float*)d_out + (size_t)MM * DD;     // [B,C,N]

    // QKV projections (tf32 mma.sync tensor cores)
    gemm_mma<0,false><<<dim3(MM/128, DD/128), 256>>>(q, Wq, bq, p_qs, MM, DD, DD);
    gemm_mma<0,false><<<dim3(MM/128, DD/128), 256>>>(k, Wk, bk, p_ks, MM, DD, DD);
    gemm_mma<0,false><<<dim3(MM/128, DD/128), 256>>>(v, Wv, bv, p_vs, MM, DD, DD);
    // attention (fp32)
    attn_kernel<<<dim3(BB*HH, NN/64), 256, ATT_SMEM>>>(p_qs, p_ks, p_vs, p_att);
    // output projection + LN1
    gemm_mma<0,false><<<dim3(MM/128, DD/128), 256>>>(p_att, Wo, bo, p_o, MM, DD, DD);
    add_ln_kernel<<<MM, 128>>>(q, p_o, ln1g, ln1b, p_x);
    // FFN
    gemm_mma<1,false><<<dim3(MM/128, DFF/128), 256>>>(p_x, W1, b1, p_ffh, MM, DD, DFF);
    gemm_mma<0,false><<<dim3(MM/128, DD/128), 256>>>(p_ffh, W2, b2, p_ff2, MM, DFF, DD);
    add_ln_kernel<<<MM, 128>>>(p_x, p_ff2, ln2g, ln2b, out_enc);
    // gate MLP (A read strided straight out of cma) + finisher
    gemm_mma<0,true><<<dim3(MM/128, GHH/128), 256>>>(cma, Wg1, bg1, p_ghr, MM, HC, GHH);
    gate_finish_kernel<<<MM, 128>>>(p_ghr, lngg, lngb, Wg2, bg2, p_gates);
    // gated fusion
    fused_kernel<<<(BB*CC*NN)/256, 256>>>(cma, p_gates, out_fused);
}

// round 4
// speedup vs baseline: 1.8657x; 1.1611x over previous
#include <cuda_runtime.h>
#include <cstdint>
#include <cmath>

// Problem constants
#define BB 16
#define NN 512
#define DD 512
#define HH 8
#define DKK 64
#define DFF 2048
#define GHH 128
#define MM (BB*NN)          // 8192
#define HC (HH*DD)          // 4096
#define CC 512              // HC / H

// ---------------- scratch (device globals; no allocation allowed) ----------
__device__ float g_qs  [MM*DD];
__device__ float g_ks  [MM*DD];
__device__ float g_vs  [MM*DD];
__device__ float g_att [MM*DD];
__device__ float g_o   [MM*DD];
__device__ float g_x   [MM*DD];
__device__ float g_ffh [MM*DFF];
__device__ float g_ff2 [MM*DD];
__device__ float g_ghr [MM*GHH];
__device__ float g_gates[MM*HH];

__device__ __forceinline__ uint32_t f2tf32(float x) {
    uint32_t r;
    asm("cvt.rna.tf32.f32 %0, %1;" : "=r"(r) : "f"(x));
    return r;
}
__device__ __forceinline__ void mma8(float* d, uint32_t a0, uint32_t a1,
                                     uint32_t a2, uint32_t a3,
                                     uint32_t b0, uint32_t b1) {
    asm volatile("mma.sync.aligned.m16n8k8.row.col.f32.tf32.tf32.f32 "
        "{%0,%1,%2,%3}, {%4,%5,%6,%7}, {%8,%9}, {%0,%1,%2,%3};"
        : "+f"(d[0]), "+f"(d[1]), "+f"(d[2]), "+f"(d[3])
        : "r"(a0), "r"(a1), "r"(a2), "r"(a3), "r"(b0), "r"(b1));
}

// ================= tf32 mma.sync GEMM: C = A @ W^T + bias =================
// CTA tile 128x128, BK=32. 256 threads = 8 warps (4 M x 2 N), warp tile 32x64.
// Register prefetch of the next K-chunk overlaps GMEM latency with math.
// ATRANS: A(m=b*512+n, k) = Abase[b*K*512 + k*512 + n]  (gate GEMM on cma)
template<int EPI, bool ATRANS>
__global__ __launch_bounds__(256)
void gemm_mma(const float* __restrict__ A, const float* __restrict__ W,
              const float* __restrict__ bias, float* __restrict__ C,
              int M, int K, int Nn) {
    __shared__ uint32_t As[32][132];   // [k][m]
    __shared__ uint32_t Bs[32][132];   // [k][n]
    const int t = threadIdx.x;
    const int lane = t & 31, wid = t >> 5;
    const int wm = (wid >> 1) * 32;
    const int wn = (wid & 1) * 64;
    const int m0 = blockIdx.x * 128, n0 = blockIdx.y * 128;
    const int g = lane >> 2, c = lane & 3;

    float acc[2][8][4];
#pragma unroll
    for (int im = 0; im < 2; im++)
#pragma unroll
        for (int jn = 0; jn < 8; jn++)
#pragma unroll
            for (int e = 0; e < 4; e++) acc[im][jn][e] = 0.f;

    float4 ra[4], rb[4];
    // prologue loads (k0 = 0)
    if (!ATRANS) {
#pragma unroll
        for (int p = 0; p < 4; p++) {
            int idx = p * 256 + t;
            ra[p] = *(const float4*)&A[(size_t)(m0 + (idx >> 3)) * K + (idx & 7) * 4];
        }
    } else {
        const int b = m0 >> 9, nb = m0 & 511;
#pragma unroll
        for (int p = 0; p < 4; p++) {
            int idx = p * 256 + t;
            ra[p] = *(const float4*)&A[(size_t)b * K * 512 +
                                       (size_t)(idx >> 5) * 512 + nb + (idx & 31) * 4];
        }
    }
#pragma unroll
    for (int p = 0; p < 4; p++) {
        int idx = p * 256 + t;
        rb[p] = *(const float4*)&W[(size_t)(n0 + (idx >> 3)) * K + (idx & 7) * 4];
    }

    for (int k0 = 0; k0 < K; k0 += 32) {
        // ---- store staged regs (converted) to smem ----
        if (!ATRANS) {
#pragma unroll
            for (int p = 0; p < 4; p++) {
                int idx = p * 256 + t;
                int row = idx >> 3, f4 = (idx & 7) * 4;
                As[f4 + 0][row] = f2tf32(ra[p].x);
                As[f4 + 1][row] = f2tf32(ra[p].y);
                As[f4 + 2][row] = f2tf32(ra[p].z);
                As[f4 + 3][row] = f2tf32(ra[p].w);
            }
        } else {
#pragma unroll
            for (int p = 0; p < 4; p++) {
                int idx = p * 256 + t;
                int kc = idx >> 5, nf = (idx & 31) * 4;
                uint4 u = {f2tf32(ra[p].x), f2tf32(ra[p].y),
                           f2tf32(ra[p].z), f2tf32(ra[p].w)};
                *(uint4*)&As[kc][nf] = u;
            }
        }
#pragma unroll
        for (int p = 0; p < 4; p++) {
            int idx = p * 256 + t;
            int row = idx >> 3, f4 = (idx & 7) * 4;
            Bs[f4 + 0][row] = f2tf32(rb[p].x);
            Bs[f4 + 1][row] = f2tf32(rb[p].y);
            Bs[f4 + 2][row] = f2tf32(rb[p].z);
            Bs[f4 + 3][row] = f2tf32(rb[p].w);
        }
        __syncthreads();
        // ---- prefetch next chunk into regs (overlaps the math below) ----
        if (k0 + 32 < K) {
            const int kn = k0 + 32;
            if (!ATRANS) {
#pragma unroll
                for (int p = 0; p < 4; p++) {
                    int idx = p * 256 + t;
                    ra[p] = *(const float4*)&A[(size_t)(m0 + (idx >> 3)) * K + kn + (idx & 7) * 4];
                }
            } else {
                const int b = m0 >> 9, nb = m0 & 511;
#pragma unroll
                for (int p = 0; p < 4; p++) {
                    int idx = p * 256 + t;
                    ra[p] = *(const float4*)&A[(size_t)b * K * 512 +
                                               (size_t)(kn + (idx >> 5)) * 512 + nb + (idx & 31) * 4];
                }
            }
#pragma unroll
            for (int p = 0; p < 4; p++) {
                int idx = p * 256 + t;
                rb[p] = *(const float4*)&W[(size_t)(n0 + (idx >> 3)) * K + kn + (idx & 7) * 4];
            }
        }
        // ---- math ----
#pragma unroll
        for (int ks = 0; ks < 32; ks += 8) {
            uint32_t af[2][4];
#pragma unroll
            for (int im = 0; im < 2; im++) {
                int m = wm + im * 16;
                af[im][0] = As[ks + c][m + g];
                af[im][1] = As[ks + c][m + g + 8];
                af[im][2] = As[ks + c + 4][m + g];
                af[im][3] = As[ks + c + 4][m + g + 8];
            }
#pragma unroll
            for (int jn = 0; jn < 8; jn++) {
                int n = wn + jn * 8;
                uint32_t b0 = Bs[ks + c][n + g];
                uint32_t b1 = Bs[ks + c + 4][n + g];
#pragma unroll
                for (int im = 0; im < 2; im++)
                    mma8(acc[im][jn], af[im][0], af[im][1], af[im][2], af[im][3], b0, b1);
            }
        }
        __syncthreads();
    }
    // ---- epilogue ----
#pragma unroll
    for (int jn = 0; jn < 8; jn++) {
        int col = n0 + wn + jn * 8 + 2 * c;
        float bv0 = bias[col], bv1 = bias[col + 1];
#pragma unroll
        for (int im = 0; im < 2; im++) {
            int row = m0 + wm + im * 16 + g;
            float v00 = acc[im][jn][0] + bv0;
            float v01 = acc[im][jn][1] + bv1;
            float v10 = acc[im][jn][2] + bv0;
            float v11 = acc[im][jn][3] + bv1;
            if (EPI == 1) {
                v00 = 0.5f * v00 * (1.f + erff(v00 * 0.70710678118654752f));
                v01 = 0.5f * v01 * (1.f + erff(v01 * 0.70710678118654752f));
                v10 = 0.5f * v10 * (1.f + erff(v10 * 0.70710678118654752f));
                v11 = 0.5f * v11 * (1.f + erff(v11 * 0.70710678118654752f));
            }
            float2 r0 = {v00, v01}, r1 = {v10, v11};
            *(float2*)&C[(size_t)row * Nn + col] = r0;
            *(float2*)&C[(size_t)(row + 8) * Nn + col] = r1;
        }
    }
}

// ================= attention via tf32 mma: per (b,h), 64 q-rows ============
// Natural-layout [row][d] tiles give conflict-free fragment LDS.
// smem: Ss[64][516] fp32, Qs[64][68] tf32, KVs[64][68] tf32, inv[64]
#define ATT_SROW 516
#define ATT_SMEM ((64*ATT_SROW + 64*68 + 64*68 + 64) * 4)

__global__ __launch_bounds__(256)
void attn_mma_kernel(const float* __restrict__ Q, const float* __restrict__ Kk,
                     const float* __restrict__ V, float* __restrict__ O) {
    extern __shared__ float sm[];
    float* Ss = sm;                              // [64][516]
    uint32_t* Qs = (uint32_t*)(sm + 64 * ATT_SROW); // [64][68]
    uint32_t* KVs = Qs + 64 * 68;                // [64][68]
    float* inv = (float*)(KVs + 64 * 68);        // [64]

    const int bh = blockIdx.x;
    const int b = bh >> 3, h = bh & 7;
    const int q0 = blockIdx.y * 64;
    const int t = threadIdx.x;
    const int lane = t & 31, wid = t >> 5;
    const int g = lane >> 2, c = lane & 3;
    const int wm = (wid >> 1) * 16;    // m-group: 16 q-rows
    const int half = wid & 1;          // key/d half (32)
    const size_t base = ((size_t)b * NN) * DD + h * DKK;
    const float scale = 0.125f;

    // ---- load Q tile [64 rows][64 d], tf32, natural layout ----
#pragma unroll
    for (int p = 0; p < 4; p++) {
        int idx = p * 256 + t;
        int r = idx >> 4, f4 = (idx & 15) * 4;
        float4 v = *(const float4*)&Q[base + (size_t)(q0 + r) * DD + f4];
        uint4 u = {f2tf32(v.x), f2tf32(v.y), f2tf32(v.z), f2tf32(v.w)};
        *(uint4*)&Qs[r * 68 + f4] = u;
    }

    // ---- pass 1: S = Q @ K^T * scale ----
    for (int c0 = 0; c0 < NN; c0 += 64) {
#pragma unroll
        for (int p = 0; p < 4; p++) {
            int idx = p * 256 + t;
            int r = idx >> 4, f4 = (idx & 15) * 4;
            float4 v = *(const float4*)&Kk[base + (size_t)(c0 + r) * DD + f4];
            uint4 u = {f2tf32(v.x), f2tf32(v.y), f2tf32(v.z), f2tf32(v.w)};
            *(uint4*)&KVs[r * 68 + f4] = u;
        }
        __syncthreads();
        float acc[4][4];
#pragma unroll
        for (int nt = 0; nt < 4; nt++)
#pragma unroll
            for (int e = 0; e < 4; e++) acc[nt][e] = 0.f;
#pragma unroll
        for (int ks = 0; ks < 8; ks++) {
            int k8 = ks * 8;
            uint32_t a0 = Qs[(wm + g) * 68 + k8 + c];
            uint32_t a1 = Qs[(wm + g + 8) * 68 + k8 + c];
            uint32_t a2 = Qs[(wm + g) * 68 + k8 + c + 4];
            uint32_t a3 = Qs[(wm + g + 8) * 68 + k8 + c + 4];
#pragma unroll
            for (int nt = 0; nt < 4; nt++) {
                int nb = half * 32 + nt * 8;
                uint32_t b0 = KVs[(nb + g) * 68 + k8 + c];
                uint32_t b1 = KVs[(nb + g) * 68 + k8 + c + 4];
                mma8(acc[nt], a0, a1, a2, a3, b0, b1);
            }
        }
#pragma unroll
        for (int nt = 0; nt < 4; nt++) {
            int col = c0 + half * 32 + nt * 8 + 2 * c;
            Ss[(wm + g) * ATT_SROW + col]         = acc[nt][0] * scale;
            Ss[(wm + g) * ATT_SROW + col + 1]     = acc[nt][1] * scale;
            Ss[(wm + g + 8) * ATT_SROW + col]     = acc[nt][2] * scale;
            Ss[(wm + g + 8) * ATT_SROW + col + 1] = acc[nt][3] * scale;
        }
        __syncthreads();
    }

    // ---- softmax (unnormalized exp + reciprocal row sums) ----
    {
        int row = t >> 2;
        int qd = t & 3;
        float* prow = &Ss[row * ATT_SROW + qd * 128];
        float mx = -1e30f;
#pragma unroll 8
        for (int i = 0; i < 128; i++) mx = fmaxf(mx, prow[i]);
        mx = fmaxf(mx, __shfl_xor_sync(0xFFFFFFFFu, mx, 1));
        mx = fmaxf(mx, __shfl_xor_sync(0xFFFFFFFFu, mx, 2));
        float sum = 0.f;
#pragma unroll 8
        for (int i = 0; i < 128; i++) {
            float e = __expf(prow[i] - mx);
            prow[i] = e;
            sum += e;
        }
        sum += __shfl_xor_sync(0xFFFFFFFFu, sum, 1);
        sum += __shfl_xor_sync(0xFFFFFFFFu, sum, 2);
        if (qd == 0) inv[row] = 1.f / sum;
    }
    __syncthreads();

    // ---- pass 2: O = P @ V ----
    float oacc[4][4];
#pragma unroll
    for (int nt = 0; nt < 4; nt++)
#pragma unroll
        for (int e = 0; e < 4; e++) oacc[nt][e] = 0.f;
    for (int c0 = 0; c0 < NN; c0 += 64) {
#pragma unroll
        for (int p = 0; p < 4; p++) {
            int idx = p * 256 + t;
            int r = idx >> 4, f4 = (idx & 15) * 4;
            float4 v = *(const float4*)&V[base + (size_t)(c0 + r) * DD + f4];
            uint4 u = {f2tf32(v.x), f2tf32(v.y), f2tf32(v.z), f2tf32(v.w)};
            *(uint4*)&KVs[r * 68 + f4] = u;
        }
        __syncthreads();
#pragma unroll
        for (int ks = 0; ks < 8; ks++) {
            int k8 = ks * 8;
            uint32_t a0 = f2tf32(Ss[(wm + g) * ATT_SROW + c0 + k8 + c]);
            uint32_t a1 = f2tf32(Ss[(wm + g + 8) * ATT_SROW + c0 + k8 + c]);
            uint32_t a2 = f2tf32(Ss[(wm + g) * ATT_SROW + c0 + k8 + c + 4]);
            uint32_t a3 = f2tf32(Ss[(wm + g + 8) * ATT_SROW + c0 + k8 + c + 4]);
#pragma unroll
            for (int nt = 0; nt < 4; nt++) {
                int d0 = half * 32 + nt * 8;
                uint32_t b0 = KVs[(k8 + c) * 68 + d0 + g];
                uint32_t b1 = KVs[(k8 + c + 4) * 68 + d0 + g];
                mma8(oacc[nt], a0, a1, a2, a3, b0, b1);
            }
        }
        __syncthreads();
    }
    // ---- epilogue: normalize and store ----
    {
        float iv0 = inv[wm + g], iv1 = inv[wm + g + 8];
#pragma unroll
        for (int nt = 0; nt < 4; nt++) {
            int col = half * 32 + nt * 8 + 2 * c;
            float2 r0 = {oacc[nt][0] * iv0, oacc[nt][1] * iv0};
            float2 r1 = {oacc[nt][2] * iv1, oacc[nt][3] * iv1};
            *(float2*)&O[base + (size_t)(q0 + wm + g) * DD + col] = r0;
            *(float2*)&O[base + (size_t)(q0 + wm + g + 8) * DD + col] = r1;
        }
    }
}

// ---------------- residual + LayerNorm over D=512 --------------------------
__global__ __launch_bounds__(128)
void add_ln_kernel(const float* __restrict__ X, const float* __restrict__ Y,
                   const float* __restrict__ g, const float* __restrict__ bt,
                   float* __restrict__ out) {
    __shared__ float sh[8];
    const int row = blockIdx.x;
    const int t = threadIdx.x;
    float4 x4 = *(const float4*)&X[(size_t)row * 512 + t * 4];
    float4 y4 = *(const float4*)&Y[(size_t)row * 512 + t * 4];
    float v[4] = {x4.x + y4.x, x4.y + y4.y, x4.z + y4.z, x4.w + y4.w};
    float s = v[0] + v[1] + v[2] + v[3];
    float s2 = v[0]*v[0] + v[1]*v[1] + v[2]*v[2] + v[3]*v[3];
#pragma unroll
    for (int off = 16; off; off >>= 1) {
        s  += __shfl_xor_sync(0xFFFFFFFFu, s, off);
        s2 += __shfl_xor_sync(0xFFFFFFFFu, s2, off);
    }
    if ((t & 31) == 0) { sh[t >> 5] = s; sh[4 + (t >> 5)] = s2; }
    __syncthreads();
    s  = sh[0] + sh[1] + sh[2] + sh[3];
    s2 = sh[4] + sh[5] + sh[6] + sh[7];
    float mean = s * (1.f / 512.f);
    float var  = s2 * (1.f / 512.f) - mean * mean;
    float rs = rsqrtf(var + 1e-5f);
    float4 g4 = *(const float4*)&g[t * 4];
    float4 b4 = *(const float4*)&bt[t * 4];
    float4 r;
    r.x = (v[0] - mean) * rs * g4.x + b4.x;
    r.y = (v[1] - mean) * rs * g4.y + b4.y;
    r.z = (v[2] - mean) * rs * g4.z + b4.z;
    r.w = (v[3] - mean) * rs * g4.w + b4.w;
    *(float4*)&out[(size_t)row * 512 + t * 4] = r;
}

// ---------------- gate finisher: LN(128) -> ReLU -> Linear(128,8) -> softmax
__global__ __launch_bounds__(128)
void gate_finish_kernel(const float* __restrict__ Hraw,
                        const float* __restrict__ lng, const float* __restrict__ lnb,
                        const float* __restrict__ Wg2, const float* __restrict__ bg2,
                        float* __restrict__ gates) {
    __shared__ float sh[8];
    __shared__ float sv[128];
    __shared__ float logits[8];
    const int row = blockIdx.x;
    const int t = threadIdx.x;
    float v = Hraw[(size_t)row * 128 + t];
    float s = v, s2 = v * v;
#pragma unroll
    for (int off = 16; off; off >>= 1) {
        s  += __shfl_xor_sync(0xFFFFFFFFu, s, off);
        s2 += __shfl_xor_sync(0xFFFFFFFFu, s2, off);
    }
    if ((t & 31) == 0) { sh[t >> 5] = s; sh[4 + (t >> 5)] = s2; }
    __syncthreads();
    s  = sh[0] + sh[1] + sh[2] + sh[3];
    s2 = sh[4] + sh[5] + sh[6] + sh[7];
    float mean = s * (1.f / 128.f);
    float var  = s2 * (1.f / 128.f) - mean * mean;
    float x = (v - mean) * rsqrtf(var + 1e-5f) * lng[t] + lnb[t];
    sv[t] = fmaxf(x, 0.f);
    __syncthreads();
    int w = t >> 5, lane = t & 31;
    for (int hh = w; hh < 8; hh += 4) {
        const float* wr = &Wg2[hh * 128];
        float p = sv[lane] * wr[lane] + sv[lane + 32] * wr[lane + 32]
                + sv[lane + 64] * wr[lane + 64] + sv[lane + 96] * wr[lane + 96];
#pragma unroll
        for (int off = 16; off; off >>= 1) p += __shfl_xor_sync(0xFFFFFFFFu, p, off);
        if (lane == 0) logits[hh] = p + bg2[hh];
    }
    __syncthreads();
    if (t == 0) {
        float mx = -1e30f;
#pragma unroll
        for (int hh = 0; hh < 8; hh++) mx = fmaxf(mx, logits[hh]);
        float e[8], sum = 0.f;
#pragma unroll
        for (int hh = 0; hh < 8; hh++) { e[hh] = __expf(logits[hh] - mx); sum += e[hh]; }
        float isum = 1.f / sum;
#pragma unroll
        for (int hh = 0; hh < 8; hh++) gates[(size_t)row * 8 + hh] = e[hh] * isum;
    }
}

// ---------------- fused = sum_h cma[b, h*C + c, n] * gates[b,n,h] ----------
__global__ __launch_bounds__(256)
void fused_kernel(const float* __restrict__ cma, const float* __restrict__ gates,
                  float* __restrict__ out) {
    int idx = blockIdx.x * 256 + threadIdx.x;
    int n = idx & 511;
    int c = (idx >> 9) & 511;
    int b = idx >> 18;
    const float* gp = &gates[((size_t)b * 512 + n) * 8];
    const float* cp = &cma[(size_t)b * HC * NN + (size_t)c * NN + n];
    float acc = 0.f;
#pragma unroll
    for (int hh = 0; hh < 8; hh++)
        acc += cp[(size_t)hh * CC * NN] * gp[hh];
    out[idx] = acc;
}

// ---------------- host launcher --------------------------------------------
extern "C" void kernel_launch(void* const* d_in, const int* in_sizes, int n_in,
                              void* d_out, int out_size) {
    const float* q    = (const float*)d_in[0];
    const float* k    = (const float*)d_in[1];
    const float* v    = (const float*)d_in[2];
    const float* cma  = (const float*)d_in[3];
    const float* Wq   = (const float*)d_in[4];
    const float* bq   = (const float*)d_in[5];
    const float* Wk   = (const float*)d_in[6];
    const float* bk   = (const float*)d_in[7];
    const float* Wv   = (const float*)d_in[8];
    const float* bv   = (const float*)d_in[9];
    const float* Wo   = (const float*)d_in[10];
    const float* bo   = (const float*)d_in[11];
    const float* ln1g = (const float*)d_in[12];
    const float* ln1b = (const float*)d_in[13];
    const float* ln2g = (const float*)d_in[14];
    const float* ln2b = (const float*)d_in[15];
    const float* W1   = (const float*)d_in[16];
    const float* b1   = (const float*)d_in[17];
    const float* W2   = (const float*)d_in[18];
    const float* b2   = (const float*)d_in[19];
    const float* Wg1  = (const float*)d_in[20];
    const float* bg1  = (const float*)d_in[21];
    const float* lngg = (const float*)d_in[22];
    const float* lngb = (const float*)d_in[23];
    const float* Wg2  = (const float*)d_in[24];
    const float* bg2  = (const float*)d_in[25];

    float *p_qs, *p_ks, *p_vs, *p_att, *p_o, *p_x, *p_ffh, *p_ff2, *p_ghr, *p_gates;
    cudaGetSymbolAddress((void**)&p_qs,  g_qs);
    cudaGetSymbolAddress((void**)&p_ks,  g_ks);
    cudaGetSymbolAddress((void**)&p_vs,  g_vs);
    cudaGetSymbolAddress((void**)&p_att, g_att);
    cudaGetSymbolAddress((void**)&p_o,   g_o);
    cudaGetSymbolAddress((void**)&p_x,   g_x);
    cudaGetSymbolAddress((void**)&p_ffh, g_ffh);
    cudaGetSymbolAddress((void**)&p_ff2, g_ff2);
    cudaGetSymbolAddress((void**)&p_ghr, g_ghr);
    cudaGetSymbolAddress((void**)&p_gates, g_gates);

    cudaFuncSetAttribute(attn_mma_kernel, cudaFuncAttributeMaxDynamicSharedMemorySize, ATT_SMEM);

    float* out_enc   = (float*)d_out;                       // [B,N,D]
    float* out_fused = (float*)d_out + (size_t)MM * DD;     // [B,C,N]

    // QKV projections (tf32 mma.sync tensor cores)
    gemm_mma<0,false><<<dim3(MM/128, DD/128), 256>>>(q, Wq, bq, p_qs, MM, DD, DD);
    gemm_mma<0,false><<<dim3(MM/128, DD/128), 256>>>(k, Wk, bk, p_ks, MM, DD, DD);
    gemm_mma<0,false><<<dim3(MM/128, DD/128), 256>>>(v, Wv, bv, p_vs, MM, DD, DD);
    // attention (tf32 mma)
    attn_mma_kernel<<<dim3(BB*HH, NN/64), 256, ATT_SMEM>>>(p_qs, p_ks, p_vs, p_att);
    // output projection + LN1
    gemm_mma<0,false><<<dim3(MM/128, DD/128), 256>>>(p_att, Wo, bo, p_o, MM, DD, DD);
    add_ln_kernel<<<MM, 128>>>(q, p_o, ln1g, ln1b, p_x);
    // FFN
    gemm_mma<1,false><<<dim3(MM/128, DFF/128), 256>>>(p_x, W1, b1, p_ffh, MM, DD, DFF);
    gemm_mma<0,false><<<dim3(MM/128, DD/128), 256>>>(p_ffh, W2, b2, p_ff2, MM, DFF, DD);
    add_ln_kernel<<<MM, 128>>>(p_x, p_ff2, ln2g, ln2b, out_enc);
    // gate MLP (A read strided straight out of cma) + finisher
    gemm_mma<0,true><<<dim3(MM/128, GHH/128), 256>>>(cma, Wg1, bg1, p_ghr, MM, HC, GHH);
    gate_finish_kernel<<<MM, 128>>>(p_ghr, lngg, lngb, Wg2, bg2, p_gates);
    // gated fusion
    fused_kernel<<<(BB*CC*NN)/256, 256>>>(cma, p_gates, out_fused);
}

// round 6
// speedup vs baseline: 2.6333x; 1.4114x over previous
#include <cuda_runtime.h>
#include <cstdint>
#include <cmath>

// Problem constants
#define BB 16
#define NN 512
#define DD 512
#define HH 8
#define DKK 64
#define DFF 2048
#define GHH 128
#define MM (BB*NN)          // 8192
#define HC (HH*DD)          // 4096
#define CC 512              // HC / H

// ---------------- scratch (device globals; no allocation allowed) ----------
__device__ float g_qs  [MM*DD];
__device__ float g_ks  [MM*DD];
__device__ float g_vs  [MM*DD];
__device__ float g_att [MM*DD];
__device__ float g_o   [MM*DD];
__device__ float g_x   [MM*DD];
__device__ float g_ffh [MM*DFF];
__device__ float g_ff2 [MM*DD];
__device__ float g_ghr [MM*GHH];
__device__ float g_gates[MM*HH];
// pre-converted (tf32-rounded) weights
__device__ float g_wq [DD*DD];
__device__ float g_wk [DD*DD];
__device__ float g_wv [DD*DD];
__device__ float g_wo [DD*DD];
__device__ float g_w1 [DFF*DD];
__device__ float g_w2 [DD*DFF];
__device__ float g_wg1[GHH*HC];

__device__ __forceinline__ uint32_t f2tf32(float x) {
    uint32_t r;
    asm("cvt.rna.tf32.f32 %0, %1;" : "=r"(r) : "f"(x));
    return r;
}
__device__ __forceinline__ void mma8(float* d, uint32_t a0, uint32_t a1,
                                     uint32_t a2, uint32_t a3,
                                     uint32_t b0, uint32_t b1) {
    asm volatile("mma.sync.aligned.m16n8k8.row.col.f32.tf32.tf32.f32 "
        "{%0,%1,%2,%3}, {%4,%5,%6,%7}, {%8,%9}, {%0,%1,%2,%3};"
        : "+f"(d[0]), "+f"(d[1]), "+f"(d[2]), "+f"(d[3])
        : "r"(a0), "r"(a1), "r"(a2), "r"(a3), "r"(b0), "r"(b1));
}
__device__ __forceinline__ uint32_t smem_u32(const void* p) {
    return (uint32_t)__cvta_generic_to_shared(p);
}
__device__ __forceinline__ void cp16(uint32_t dst, const float* src) {
    asm volatile("cp.async.cg.shared.global [%0], [%1], 16;" :: "r"(dst), "l"(src));
}

// ---------------- weight pre-conversion to tf32 bits ----------------------
__global__ __launch_bounds__(256)
void cvt_tf32_kernel(const float* __restrict__ src, float* __restrict__ dst, int n) {
    int i = (blockIdx.x * 256 + threadIdx.x) * 4;
    if (i < n) {
        float4 v = *(const float4*)&src[i];
        uint4 u = {f2tf32(v.x), f2tf32(v.y), f2tf32(v.z), f2tf32(v.w)};
        *(uint4*)&dst[i] = u;
    }
}

// ================= tf32 mma.sync GEMM: C = A @ W^T + bias =================
// CTA tile 128x128, BK=32, 3-stage cp.async pipeline, 256 threads = 8 warps.
// A smem [m][36] (k-contig), B smem [n][36] (k-contig, pre-rounded tf32 bits).
// ATRANS: A(m=b*512+n, k) = Abase[b*K*512 + k*512 + n]; smem [k][132].
template<int EPI, bool ATRANS>
__device__ __forceinline__ void issue_stage(
    const float* __restrict__ A, const float* __restrict__ W,
    int K, int m0, int n0, int k0, int t, uint32_t sA, uint32_t sB) {
    if (!ATRANS) {
#pragma unroll
        for (int p = 0; p < 4; p++) {
            int idx = p * 256 + t;
            int row = idx >> 3, f4 = idx & 7;
            cp16(sA + (uint32_t)(row * 36 + f4 * 4) * 4,
                 &A[(size_t)(m0 + row) * K + k0 + f4 * 4]);
        }
    } else {
        const int b = m0 >> 9, nb = m0 & 511;
#pragma unroll
        for (int p = 0; p < 4; p++) {
            int idx = p * 256 + t;
            int kc = idx >> 5, nf = idx & 31;
            cp16(sA + (uint32_t)(kc * 132 + nf * 4) * 4,
                 &A[(size_t)b * K * 512 + (size_t)(k0 + kc) * 512 + nb + nf * 4]);
        }
    }
#pragma unroll
    for (int p = 0; p < 4; p++) {
        int idx = p * 256 + t;
        int row = idx >> 3, f4 = idx & 7;
        cp16(sB + (uint32_t)(row * 36 + f4 * 4) * 4,
             &W[(size_t)(n0 + row) * K + k0 + f4 * 4]);
    }
    asm volatile("cp.async.commit_group;" ::: "memory");
}

template<int EPI, bool ATRANS>
__global__ __launch_bounds__(256, 2)
void gemm_mma(const float* __restrict__ A, const float* __restrict__ W,
              const float* __restrict__ bias, float* __restrict__ C,
              int M, int K, int Nn) {
    constexpr int ASZ = ATRANS ? 32 * 132 : 128 * 36;
    constexpr int BSZ = 128 * 36;
    constexpr int STG = ASZ + BSZ;
    extern __shared__ float smem[];
    const uint32_t sbase = smem_u32(smem);
    const int t = threadIdx.x;
    const int lane = t & 31, wid = t >> 5;
    const int wm = (wid >> 1) * 32;
    const int wn = (wid & 1) * 64;
    const int m0 = blockIdx.x * 128, n0 = blockIdx.y * 128;
    const int g = lane >> 2, c = lane & 3;
    const int NSTEP = K / 32;

    float acc[2][8][4];
#pragma unroll
    for (int im = 0; im < 2; im++)
#pragma unroll
        for (int jn = 0; jn < 8; jn++)
#pragma unroll
            for (int e = 0; e < 4; e++) acc[im][jn][e] = 0.f;

    // prologue: stages 0, 1
    issue_stage<EPI, ATRANS>(A, W, K, m0, n0, 0,  t, sbase, sbase + ASZ * 4);
    issue_stage<EPI, ATRANS>(A, W, K, m0, n0, 32, t, sbase + STG * 4, sbase + (STG + ASZ) * 4);

    for (int s = 0; s < NSTEP; s++) {
        if (s == NSTEP - 1)
            asm volatile("cp.async.wait_group 0;" ::: "memory");
        else
            asm volatile("cp.async.wait_group 1;" ::: "memory");
        __syncthreads();
        if (s + 2 < NSTEP) {
            int st = (s + 2) % 3;
            issue_stage<EPI, ATRANS>(A, W, K, m0, n0, (s + 2) * 32, t,
                                     sbase + (uint32_t)(st * STG) * 4,
                                     sbase + (uint32_t)(st * STG + ASZ) * 4);
        }
        const uint32_t* As = (const uint32_t*)(smem + (s % 3) * STG);
        const uint32_t* Bs = As + ASZ;
#pragma unroll
        for (int ks = 0; ks < 4; ks++) {
            const int k8 = ks * 8;
            uint32_t af[2][4];
#pragma unroll
            for (int im = 0; im < 2; im++) {
                const int m = wm + im * 16;
                uint32_t r0, r1, r2, r3;
                if (!ATRANS) {
                    r0 = As[(m + g) * 36 + k8 + c];
                    r1 = As[(m + g + 8) * 36 + k8 + c];
                    r2 = As[(m + g) * 36 + k8 + c + 4];
                    r3 = As[(m + g + 8) * 36 + k8 + c + 4];
                } else {
                    r0 = As[(k8 + c) * 132 + m + g];
                    r1 = As[(k8 + c) * 132 + m + g + 8];
                    r2 = As[(k8 + c + 4) * 132 + m + g];
                    r3 = As[(k8 + c + 4) * 132 + m + g + 8];
                }
                af[im][0] = f2tf32(__uint_as_float(r0));
                af[im][1] = f2tf32(__uint_as_float(r1));
                af[im][2] = f2tf32(__uint_as_float(r2));
                af[im][3] = f2tf32(__uint_as_float(r3));
            }
#pragma unroll
            for (int jn = 0; jn < 8; jn++) {
                const int n = wn + jn * 8;
                uint32_t b0 = Bs[(n + g) * 36 + k8 + c];
                uint32_t b1 = Bs[(n + g) * 36 + k8 + c + 4];
#pragma unroll
                for (int im = 0; im < 2; im++)
                    mma8(acc[im][jn], af[im][0], af[im][1], af[im][2], af[im][3], b0, b1);
            }
        }
        __syncthreads();
    }
    // ---- epilogue ----
#pragma unroll
    for (int jn = 0; jn < 8; jn++) {
        int col = n0 + wn + jn * 8 + 2 * c;
        float bv0 = bias[col], bv1 = bias[col + 1];
#pragma unroll
        for (int im = 0; im < 2; im++) {
            int row = m0 + wm + im * 16 + g;
            float v00 = acc[im][jn][0] + bv0;
            float v01 = acc[im][jn][1] + bv1;
            float v10 = acc[im][jn][2] + bv0;
            float v11 = acc[im][jn][3] + bv1;
            if (EPI == 1) {
                v00 = 0.5f * v00 * (1.f + erff(v00 * 0.70710678118654752f));
                v01 = 0.5f * v01 * (1.f + erff(v01 * 0.70710678118654752f));
                v10 = 0.5f * v10 * (1.f + erff(v10 * 0.70710678118654752f));
                v11 = 0.5f * v11 * (1.f + erff(v11 * 0.70710678118654752f));
            }
            float2 r0 = {v00, v01}, r1 = {v10, v11};
            *(float2*)&C[(size_t)row * Nn + col] = r0;
            *(float2*)&C[(size_t)(row + 8) * Nn + col] = r1;
        }
    }
}

// ================= attention via tf32 mma: per (b,h), 64 q-rows ============
#define ATT_SROW 516
#define ATT_SMEM ((64*ATT_SROW + 64*68 + 64*68 + 64) * 4)

__global__ __launch_bounds__(256)
void attn_mma_kernel(const float* __restrict__ Q, const float* __restrict__ Kk,
                     const float* __restrict__ V, float* __restrict__ O) {
    extern __shared__ float sm[];
    float* Ss = sm;                                 // [64][516]
    uint32_t* Qs = (uint32_t*)(sm + 64 * ATT_SROW); // [64][68]
    uint32_t* KVs = Qs + 64 * 68;                   // [64][68]
    float* inv = (float*)(KVs + 64 * 68);           // [64]

    const int bh = blockIdx.x;
    const int b = bh >> 3, h = bh & 7;
    const int q0 = blockIdx.y * 64;
    const int t = threadIdx.x;
    const int lane = t & 31, wid = t >> 5;
    const int g = lane >> 2, c = lane & 3;
    const int wm = (wid >> 1) * 16;
    const int half = wid & 1;
    const size_t base = ((size_t)b * NN) * DD + h * DKK;
    const float scale = 0.125f;

#pragma unroll
    for (int p = 0; p < 4; p++) {
        int idx = p * 256 + t;
        int r = idx >> 4, f4 = (idx & 15) * 4;
        float4 v = *(const float4*)&Q[base + (size_t)(q0 + r) * DD + f4];
        uint4 u = {f2tf32(v.x), f2tf32(v.y), f2tf32(v.z), f2tf32(v.w)};
        *(uint4*)&Qs[r * 68 + f4] = u;
    }

    for (int c0 = 0; c0 < NN; c0 += 64) {
#pragma unroll
        for (int p = 0; p < 4; p++) {
            int idx = p * 256 + t;
            int r = idx >> 4, f4 = (idx & 15) * 4;
            float4 v = *(const float4*)&Kk[base + (size_t)(c0 + r) * DD + f4];
            uint4 u = {f2tf32(v.x), f2tf32(v.y), f2tf32(v.z), f2tf32(v.w)};
            *(uint4*)&KVs[r * 68 + f4] = u;
        }
        __syncthreads();
        float acc[4][4];
#pragma unroll
        for (int nt = 0; nt < 4; nt++)
#pragma unroll
            for (int e = 0; e < 4; e++) acc[nt][e] = 0.f;
#pragma unroll
        for (int ks = 0; ks < 8; ks++) {
            int k8 = ks * 8;
            uint32_t a0 = Qs[(wm + g) * 68 + k8 + c];
            uint32_t a1 = Qs[(wm + g + 8) * 68 + k8 + c];
            uint32_t a2 = Qs[(wm + g) * 68 + k8 + c + 4];
            uint32_t a3 = Qs[(wm + g + 8) * 68 + k8 + c + 4];
#pragma unroll
            for (int nt = 0; nt < 4; nt++) {
                int nb = half * 32 + nt * 8;
                uint32_t b0 = KVs[(nb + g) * 68 + k8 + c];
                uint32_t b1 = KVs[(nb + g) * 68 + k8 + c + 4];
                mma8(acc[nt], a0, a1, a2, a3, b0, b1);
            }
        }
#pragma unroll
        for (int nt = 0; nt < 4; nt++) {
            int col = c0 + half * 32 + nt * 8 + 2 * c;
            Ss[(wm + g) * ATT_SROW + col]         = acc[nt][0] * scale;
            Ss[(wm + g) * ATT_SROW + col + 1]     = acc[nt][1] * scale;
            Ss[(wm + g + 8) * ATT_SROW + col]     = acc[nt][2] * scale;
            Ss[(wm + g + 8) * ATT_SROW + col + 1] = acc[nt][3] * scale;
        }
        __syncthreads();
    }

    {
        int row = t >> 2;
        int qd = t & 3;
        float* prow = &Ss[row * ATT_SROW + qd * 128];
        float mx = -1e30f;
#pragma unroll 8
        for (int i = 0; i < 128; i++) mx = fmaxf(mx, prow[i]);
        mx = fmaxf(mx, __shfl_xor_sync(0xFFFFFFFFu, mx, 1));
        mx = fmaxf(mx, __shfl_xor_sync(0xFFFFFFFFu, mx, 2));
        float sum = 0.f;
#pragma unroll 8
        for (int i = 0; i < 128; i++) {
            float e = __expf(prow[i] - mx);
            prow[i] = e;
            sum += e;
        }
        sum += __shfl_xor_sync(0xFFFFFFFFu, sum, 1);
        sum += __shfl_xor_sync(0xFFFFFFFFu, sum, 2);
        if (qd == 0) inv[row] = 1.f / sum;
    }
    __syncthreads();

    float oacc[4][4];
#pragma unroll
    for (int nt = 0; nt < 4; nt++)
#pragma unroll
        for (int e = 0; e < 4; e++) oacc[nt][e] = 0.f;
    for (int c0 = 0; c0 < NN; c0 += 64) {
#pragma unroll
        for (int p = 0; p < 4; p++) {
            int idx = p * 256 + t;
            int r = idx >> 4, f4 = (idx & 15) * 4;
            float4 v = *(const float4*)&V[base + (size_t)(c0 + r) * DD + f4];
            uint4 u = {f2tf32(v.x), f2tf32(v.y), f2tf32(v.z), f2tf32(v.w)};
            *(uint4*)&KVs[r * 68 + f4] = u;
        }
        __syncthreads();
#pragma unroll
        for (int ks = 0; ks < 8; ks++) {
            int k8 = ks * 8;
            uint32_t a0 = f2tf32(Ss[(wm + g) * ATT_SROW + c0 + k8 + c]);
            uint32_t a1 = f2tf32(Ss[(wm + g + 8) * ATT_SROW + c0 + k8 + c]);
            uint32_t a2 = f2tf32(Ss[(wm + g) * ATT_SROW + c0 + k8 + c + 4]);
            uint32_t a3 = f2tf32(Ss[(wm + g + 8) * ATT_SROW + c0 + k8 + c + 4]);
#pragma unroll
            for (int nt = 0; nt < 4; nt++) {
                int d0 = half * 32 + nt * 8;
                uint32_t b0 = KVs[(k8 + c) * 68 + d0 + g];
                uint32_t b1 = KVs[(k8 + c + 4) * 68 + d0 + g];
                mma8(oacc[nt], a0, a1, a2, a3, b0, b1);
            }
        }
        __syncthreads();
    }
    {
        float iv0 = inv[wm + g], iv1 = inv[wm + g + 8];
#pragma unroll
        for (int nt = 0; nt < 4; nt++) {
            int col = half * 32 + nt * 8 + 2 * c;
            float2 r0 = {oacc[nt][0] * iv0, oacc[nt][1] * iv0};
            float2 r1 = {oacc[nt][2] * iv1, oacc[nt][3] * iv1};
            *(float2*)&O[base + (size_t)(q0 + wm + g) * DD + col] = r0;
            *(float2*)&O[base + (size_t)(q0 + wm + g + 8) * DD + col] = r1;
        }
    }
}

// ---------------- residual + LayerNorm over D=512 --------------------------
__global__ __launch_bounds__(128)
void add_ln_kernel(const float* __restrict__ X, const float* __restrict__ Y,
                   const float* __restrict__ g, const float* __restrict__ bt,
                   float* __restrict__ out) {
    __shared__ float sh[8];
    const int row = blockIdx.x;
    const int t = threadIdx.x;
    float4 x4 = *(const float4*)&X[(size_t)row * 512 + t * 4];
    float4 y4 = *(const float4*)&Y[(size_t)row * 512 + t * 4];
    float v[4] = {x4.x + y4.x, x4.y + y4.y, x4.z + y4.z, x4.w + y4.w};
    float s = v[0] + v[1] + v[2] + v[3];
    float s2 = v[0]*v[0] + v[1]*v[1] + v[2]*v[2] + v[3]*v[3];
#pragma unroll
    for (int off = 16; off; off >>= 1) {
        s  += __shfl_xor_sync(0xFFFFFFFFu, s, off);
        s2 += __shfl_xor_sync(0xFFFFFFFFu, s2, off);
    }
    if ((t & 31) == 0) { sh[t >> 5] = s; sh[4 + (t >> 5)] = s2; }
    __syncthreads();
    s  = sh[0] + sh[1] + sh[2] + sh[3];
    s2 = sh[4] + sh[5] + sh[6] + sh[7];
    float mean = s * (1.f / 512.f);
    float var  = s2 * (1.f / 512.f) - mean * mean;
    float rs = rsqrtf(var + 1e-5f);
    float4 g4 = *(const float4*)&g[t * 4];
    float4 b4 = *(const float4*)&bt[t * 4];
    float4 r;
    r.x = (v[0] - mean) * rs * g4.x + b4.x;
    r.y = (v[1] - mean) * rs * g4.y + b4.y;
    r.z = (v[2] - mean) * rs * g4.z + b4.z;
    r.w = (v[3] - mean) * rs * g4.w + b4.w;
    *(float4*)&out[(size_t)row * 512 + t * 4] = r;
}

// ---------------- gate finisher: LN(128) -> ReLU -> Linear(128,8) -> softmax
__global__ __launch_bounds__(128)
void gate_finish_kernel(const float* __restrict__ Hraw,
                        const float* __restrict__ lng, const float* __restrict__ lnb,
                        const float* __restrict__ Wg2, const float* __restrict__ bg2,
                        float* __restrict__ gates) {
    __shared__ float sh[8];
    __shared__ float sv[128];
    __shared__ float logits[8];
    const int row = blockIdx.x;
    const int t = threadIdx.x;
    float v = Hraw[(size_t)row * 128 + t];
    float s = v, s2 = v * v;
#pragma unroll
    for (int off = 16; off; off >>= 1) {
        s  += __shfl_xor_sync(0xFFFFFFFFu, s, off);
        s2 += __shfl_xor_sync(0xFFFFFFFFu, s2, off);
    }
    if ((t & 31) == 0) { sh[t >> 5] = s; sh[4 + (t >> 5)] = s2; }
    __syncthreads();
    s  = sh[0] + sh[1] + sh[2] + sh[3];
    s2 = sh[4] + sh[5] + sh[6] + sh[7];
    float mean = s * (1.f / 128.f);
    float var  = s2 * (1.f / 128.f) - mean * mean;
    float x = (v - mean) * rsqrtf(var + 1e-5f) * lng[t] + lnb[t];
    sv[t] = fmaxf(x, 0.f);
    __syncthreads();
    int w = t >> 5, lane = t & 31;
    for (int hh = w; hh < 8; hh += 4) {
        const float* wr = &Wg2[hh * 128];
        float p = sv[lane] * wr[lane] + sv[lane + 32] * wr[lane + 32]
                + sv[lane + 64] * wr[lane + 64] + sv[lane + 96] * wr[lane + 96];
#pragma unroll
        for (int off = 16; off; off >>= 1) p += __shfl_xor_sync(0xFFFFFFFFu, p, off);
        if (lane == 0) logits[hh] = p + bg2[hh];
    }
    __syncthreads();
    if (t == 0) {
        float mx = -1e30f;
#pragma unroll
        for (int hh = 0; hh < 8; hh++) mx = fmaxf(mx, logits[hh]);
        float e[8], sum = 0.f;
#pragma unroll
        for (int hh = 0; hh < 8; hh++) { e[hh] = __expf(logits[hh] - mx); sum += e[hh]; }
        float isum = 1.f / sum;
#pragma unroll
        for (int hh = 0; hh < 8; hh++) gates[(size_t)row * 8 + hh] = e[hh] * isum;
    }
}

// ---------------- fused = sum_h cma[b, h*C + c, n] * gates[b,n,h] ----------
__global__ __launch_bounds__(256)
void fused_kernel(const float* __restrict__ cma, const float* __restrict__ gates,
                  float* __restrict__ out) {
    int idx = blockIdx.x * 256 + threadIdx.x;
    int n = idx & 511;
    int c = (idx >> 9) & 511;
    int b = idx >> 18;
    const float* gp = &gates[((size_t)b * 512 + n) * 8];
    const float* cp = &cma[(size_t)b * HC * NN + (size_t)c * NN + n];
    float acc = 0.f;
#pragma unroll
    for (int hh = 0; hh < 8; hh++)
        acc += cp[(size_t)hh * CC * NN] * gp[hh];
    out[idx] = acc;
}

// ---------------- host launcher --------------------------------------------
extern "C" void kernel_launch(void* const* d_in, const int* in_sizes, int n_in,
                              void* d_out, int out_size) {
    const float* q    = (const float*)d_in[0];
    const float* k    = (const float*)d_in[1];
    const float* v    = (const float*)d_in[2];
    const float* cma  = (const float*)d_in[3];
    const float* Wq   = (const float*)d_in[4];
    const float* bq   = (const float*)d_in[5];
    const float* Wk   = (const float*)d_in[6];
    const float* bk   = (const float*)d_in[7];
    const float* Wv   = (const float*)d_in[8];
    const float* bv   = (const float*)d_in[9];
    const float* Wo   = (const float*)d_in[10];
    const float* bo   = (const float*)d_in[11];
    const float* ln1g = (const float*)d_in[12];
    const float* ln1b = (const float*)d_in[13];
    const float* ln2g = (const float*)d_in[14];
    const float* ln2b = (const float*)d_in[15];
    const float* W1   = (const float*)d_in[16];
    const float* b1   = (const float*)d_in[17];
    const float* W2   = (const float*)d_in[18];
    const float* b2   = (const float*)d_in[19];
    const float* Wg1  = (const float*)d_in[20];
    const float* bg1  = (const float*)d_in[21];
    const float* lngg = (const float*)d_in[22];
    const float* lngb = (const float*)d_in[23];
    const float* Wg2  = (const float*)d_in[24];
    const float* bg2  = (const float*)d_in[25];

    float *p_qs, *p_ks, *p_vs, *p_att, *p_o, *p_x, *p_ffh, *p_ff2, *p_ghr, *p_gates;
    float *p_wq, *p_wk, *p_wv, *p_wo, *p_w1, *p_w2, *p_wg1;
    cudaGetSymbolAddress((void**)&p_qs,  g_qs);
    cudaGetSymbolAddress((void**)&p_ks,  g_ks);
    cudaGetSymbolAddress((void**)&p_vs,  g_vs);
    cudaGetSymbolAddress((void**)&p_att, g_att);
    cudaGetSymbolAddress((void**)&p_o,   g_o);
    cudaGetSymbolAddress((void**)&p_x,   g_x);
    cudaGetSymbolAddress((void**)&p_ffh, g_ffh);
    cudaGetSymbolAddress((void**)&p_ff2, g_ff2);
    cudaGetSymbolAddress((void**)&p_ghr, g_ghr);
    cudaGetSymbolAddress((void**)&p_gates, g_gates);
    cudaGetSymbolAddress((void**)&p_wq,  g_wq);
    cudaGetSymbolAddress((void**)&p_wk,  g_wk);
    cudaGetSymbolAddress((void**)&p_wv,  g_wv);
    cudaGetSymbolAddress((void**)&p_wo,  g_wo);
    cudaGetSymbolAddress((void**)&p_w1,  g_w1);
    cudaGetSymbolAddress((void**)&p_w2,  g_w2);
    cudaGetSymbolAddress((void**)&p_wg1, g_wg1);

    constexpr int SM_N = 3 * (128 * 36 + 128 * 36) * 4;   // 110592
    constexpr int SM_T = 3 * (32 * 132 + 128 * 36) * 4;   // 105984
    cudaFuncSetAttribute(attn_mma_kernel, cudaFuncAttributeMaxDynamicSharedMemorySize, ATT_SMEM);
    cudaFuncSetAttribute(gemm_mma<0,false>, cudaFuncAttributeMaxDynamicSharedMemorySize, SM_N);
    cudaFuncSetAttribute(gemm_mma<1,false>, cudaFuncAttributeMaxDynamicSharedMemorySize, SM_N);
    cudaFuncSetAttribute(gemm_mma<0,true>,  cudaFuncAttributeMaxDynamicSharedMemorySize, SM_T);

    float* out_enc   = (float*)d_out;                       // [B,N,D]
    float* out_fused = (float*)d_out + (size_t)MM * DD;     // [B,C,N]

    // pre-round all weights to tf32 bits (reused across the whole graph)
    cvt_tf32_kernel<<<DD*DD/1024, 256>>>(Wq, p_wq, DD*DD);
    cvt_tf32_kernel<<<DD*DD/1024, 256>>>(Wk, p_wk, DD*DD);
    cvt_tf32_kernel<<<DD*DD/1024, 256>>>(Wv, p_wv, DD*DD);
    cvt_tf32_kernel<<<DD*DD/1024, 256>>>(Wo, p_wo, DD*DD);
    cvt_tf32_kernel<<<DFF*DD/1024, 256>>>(W1, p_w1, DFF*DD);
    cvt_tf32_kernel<<<DD*DFF/1024, 256>>>(W2, p_w2, DD*DFF);
    cvt_tf32_kernel<<<GHH*HC/1024, 256>>>(Wg1, p_wg1, GHH*HC);

    // QKV projections
    gemm_mma<0,false><<<dim3(MM/128, DD/128), 256, SM_N>>>(q, p_wq, bq, p_qs, MM, DD, DD);
    gemm_mma<0,false><<<dim3(MM/128, DD/128), 256, SM_N>>>(k, p_wk, bk, p_ks, MM, DD, DD);
    gemm_mma<0,false><<<dim3(MM/128, DD/128), 256, SM_N>>>(v, p_wv, bv, p_vs, MM, DD, DD);
    // attention (tf32 mma)
    attn_mma_kernel<<<dim3(BB*HH, NN/64), 256, ATT_SMEM>>>(p_qs, p_ks, p_vs, p_att);
    // output projection + LN1
    gemm_mma<0,false><<<dim3(MM/128, DD/128), 256, SM_N>>>(p_att, p_wo, bo, p_o, MM, DD, DD);
    add_ln_kernel<<<MM, 128>>>(q, p_o, ln1g, ln1b, p_x);
    // FFN
    gemm_mma<1,false><<<dim3(MM/128, DFF/128), 256, SM_N>>>(p_x, p_w1, b1, p_ffh, MM, DD, DFF);
    gemm_mma<0,false><<<dim3(MM/128, DD/128), 256, SM_N>>>(p_ffh, p_w2, b2, p_ff2, MM, DFF, DD);
    add_ln_kernel<<<MM, 128>>>(p_x, p_ff2, ln2g, ln2b, out_enc);
    // gate MLP (A read strided straight out of cma) + finisher
    gemm_mma<0,true><<<dim3(MM/128, GHH/128), 256, SM_T>>>(cma, p_wg1, bg1, p_ghr, MM, HC, GHH);
    gate_finish_kernel<<<MM, 128>>>(p_ghr, lngg, lngb, Wg2, bg2, p_gates);
    // gated fusion
    fused_kernel<<<(BB*CC*NN)/256, 256>>>(cma, p_gates, out_fused);
}

// round 13
// speedup vs baseline: 3.0220x; 1.1476x over previous
#include <cuda_runtime.h>
#include <cstdint>
#include <cmath>

// Problem constants
#define BB 16
#define NN 512
#define DD 512
#define HH 8
#define DKK 64
#define DFF 2048
#define GHH 128
#define MM (BB*NN)          // 8192
#define HC (HH*DD)          // 4096
#define CC 512              // HC / H

// ---------------- scratch (device globals; no allocation allowed) ----------
__device__ float g_qkv [MM*3*DD];     // packed QKV output [8192][1536]
__device__ float g_att [MM*DD];
__device__ float g_o   [MM*DD];
__device__ float g_x   [MM*DD];
__device__ float g_ffh [MM*DFF];
__device__ float g_ff2 [MM*DD];
__device__ float g_ghr [MM*GHH];
__device__ float g_gates[MM*HH];
// pre-converted (tf32-rounded) weights
__device__ float g_wqkv[3*DD*DD];     // [1536][512]  rows: Wq | Wk | Wv
__device__ float g_bqkv[3*DD];
__device__ float g_wo [DD*DD];
__device__ float g_w1 [DFF*DD];
__device__ float g_w2 [DD*DFF];
__device__ float g_wg1[GHH*HC];

__device__ __forceinline__ uint32_t f2tf32(float x) {
    uint32_t r;
    asm("cvt.rna.tf32.f32 %0, %1;" : "=r"(r) : "f"(x));
    return r;
}
__device__ __forceinline__ void mma8(float* d, uint32_t a0, uint32_t a1,
                                     uint32_t a2, uint32_t a3,
                                     uint32_t b0, uint32_t b1) {
    asm volatile("mma.sync.aligned.m16n8k8.row.col.f32.tf32.tf32.f32 "
        "{%0,%1,%2,%3}, {%4,%5,%6,%7}, {%8,%9}, {%0,%1,%2,%3};"
        : "+f"(d[0]), "+f"(d[1]), "+f"(d[2]), "+f"(d[3])
        : "r"(a0), "r"(a1), "r"(a2), "r"(a3), "r"(b0), "r"(b1));
}
__device__ __forceinline__ uint32_t smem_u32(const void* p) {
    return (uint32_t)__cvta_generic_to_shared(p);
}
__device__ __forceinline__ void cp16(uint32_t dst, const float* src) {
    asm volatile("cp.async.cg.shared.global [%0], [%1], 16;" :: "r"(dst), "l"(src));
}

// ---------------- weight pre-conversion / packing --------------------------
__global__ __launch_bounds__(256)
void cvt_tf32_kernel(const float* __restrict__ src, float* __restrict__ dst, int n) {
    int i = (blockIdx.x * 256 + threadIdx.x) * 4;
    if (i < n) {
        float4 v = *(const float4*)&src[i];
        uint4 u = {f2tf32(v.x), f2tf32(v.y), f2tf32(v.z), f2tf32(v.w)};
        *(uint4*)&dst[i] = u;
    }
}
__global__ __launch_bounds__(256)
void pack_qkv_w_kernel(const float* __restrict__ Wq, const float* __restrict__ Wk,
                       const float* __restrict__ Wv, float* __restrict__ dst) {
    int i = (blockIdx.x * 256 + threadIdx.x) * 4;   // over 1536*512
    int row = i >> 9, col = i & 511;
    const float* src = (row < 512) ? &Wq[(size_t)row * 512]
                     : (row < 1024) ? &Wk[(size_t)(row - 512) * 512]
                                    : &Wv[(size_t)(row - 1024) * 512];
    float4 v = *(const float4*)&src[col];
    uint4 u = {f2tf32(v.x), f2tf32(v.y), f2tf32(v.z), f2tf32(v.w)};
    *(uint4*)&dst[i] = u;
}
__global__ __launch_bounds__(256)
void pack_qkv_b_kernel(const float* __restrict__ bq, const float* __restrict__ bk,
                       const float* __restrict__ bv, float* __restrict__ dst) {
    int i = blockIdx.x * 256 + threadIdx.x;         // over 1536
    dst[i] = (i < 512) ? bq[i] : (i < 1024) ? bk[i - 512] : bv[i - 1024];
}

// ================= tf32 mma.sync GEMM: C = A @ W^T + bias =================
// CTA tile 128x128, BK=32, 3-stage cp.async pipeline, 256 threads = 8 warps.
// FUSE3: blockIdx.z selects A from {A, A1, A2} (q/k/v cross-attention inputs);
//        n0 gains +z*512 so packed weight/bias/output columns line up.
// ATRANS: A(m=b*512+n, k) = Abase[b*K*512 + k*512 + n]; smem [k][132].
template<int EPI, bool ATRANS>
__device__ __forceinline__ void issue_stage(
    const float* __restrict__ A, const float* __restrict__ W,
    int K, int m0, int n0, int k0, int t, uint32_t sA, uint32_t sB) {
    if (!ATRANS) {
#pragma unroll
        for (int p = 0; p < 4; p++) {
            int idx = p * 256 + t;
            int row = idx >> 3, f4 = idx & 7;
            cp16(sA + (uint32_t)(row * 36 + f4 * 4) * 4,
                 &A[(size_t)(m0 + row) * K + k0 + f4 * 4]);
        }
    } else {
        const int b = m0 >> 9, nb = m0 & 511;
#pragma unroll
        for (int p = 0; p < 4; p++) {
            int idx = p * 256 + t;
            int kc = idx >> 5, nf = idx & 31;
            cp16(sA + (uint32_t)(kc * 132 + nf * 4) * 4,
                 &A[(size_t)b * K * 512 + (size_t)(k0 + kc) * 512 + nb + nf * 4]);
        }
    }
#pragma unroll
    for (int p = 0; p < 4; p++) {
        int idx = p * 256 + t;
        int row = idx >> 3, f4 = idx & 7;
        cp16(sB + (uint32_t)(row * 36 + f4 * 4) * 4,
             &W[(size_t)(n0 + row) * K + k0 + f4 * 4]);
    }
    asm volatile("cp.async.commit_group;" ::: "memory");
}

template<int EPI, bool ATRANS, bool FUSE3>
__global__ __launch_bounds__(256, 2)
void gemm_mma(const float* __restrict__ A, const float* __restrict__ W,
              const float* __restrict__ bias, float* __restrict__ C,
              int M, int K, int Nn,
              const float* __restrict__ A1, const float* __restrict__ A2) {
    constexpr int ASZ = ATRANS ? 32 * 132 : 128 * 36;
    constexpr int BSZ = 128 * 36;
    constexpr int STG = ASZ + BSZ;
    extern __shared__ float smem[];
    const uint32_t sbase = smem_u32(smem);
    const int t = threadIdx.x;
    const int lane = t & 31, wid = t >> 5;
    const int wm = (wid >> 1) * 32;
    const int wn = (wid & 1) * 64;
    const int m0 = blockIdx.x * 128;
    int n0 = blockIdx.y * 128;
    const float* Ax = A;
    if (FUSE3) {
        const int z = blockIdx.z;
        Ax = (z == 0) ? A : (z == 1) ? A1 : A2;
        n0 += z * 512;
    }
    const int g = lane >> 2, c = lane & 3;
    const int NSTEP = K / 32;

    float acc[2][8][4];
#pragma unroll
    for (int im = 0; im < 2; im++)
#pragma unroll
        for (int jn = 0; jn < 8; jn++)
#pragma unroll
            for (int e = 0; e < 4; e++) acc[im][jn][e] = 0.f;

    issue_stage<EPI, ATRANS>(Ax, W, K, m0, n0, 0,  t, sbase, sbase + ASZ * 4);
    issue_stage<EPI, ATRANS>(Ax, W, K, m0, n0, 32, t, sbase + STG * 4, sbase + (STG + ASZ) * 4);

    for (int s = 0; s < NSTEP; s++) {
        if (s == NSTEP - 1)
            asm volatile("cp.async.wait_group 0;" ::: "memory");
        else
            asm volatile("cp.async.wait_group 1;" ::: "memory");
        __syncthreads();
        if (s + 2 < NSTEP) {
            int st = (s + 2) % 3;
            issue_stage<EPI, ATRANS>(Ax, W, K, m0, n0, (s + 2) * 32, t,
                                     sbase + (uint32_t)(st * STG) * 4,
                                     sbase + (uint32_t)(st * STG + ASZ) * 4);
        }
        const uint32_t* As = (const uint32_t*)(smem + (s % 3) * STG);
        const uint32_t* Bs = As + ASZ;
#pragma unroll
        for (int ks = 0; ks < 4; ks++) {
            const int k8 = ks * 8;
            uint32_t af[2][4];
#pragma unroll
            for (int im = 0; im < 2; im++) {
                const int m = wm + im * 16;
                uint32_t r0, r1, r2, r3;
                if (!ATRANS) {
                    r0 = As[(m + g) * 36 + k8 + c];
                    r1 = As[(m + g + 8) * 36 + k8 + c];
                    r2 = As[(m + g) * 36 + k8 + c + 4];
                    r3 = As[(m + g + 8) * 36 + k8 + c + 4];
                } else {
                    r0 = As[(k8 + c) * 132 + m + g];
                    r1 = As[(k8 + c) * 132 + m + g + 8];
                    r2 = As[(k8 + c + 4) * 132 + m + g];
                    r3 = As[(k8 + c + 4) * 132 + m + g + 8];
                }
                af[im][0] = f2tf32(__uint_as_float(r0));
                af[im][1] = f2tf32(__uint_as_float(r1));
                af[im][2] = f2tf32(__uint_as_float(r2));
                af[im][3] = f2tf32(__uint_as_float(r3));
            }
#pragma unroll
            for (int jn = 0; jn < 8; jn++) {
                const int n = wn + jn * 8;
                uint32_t b0 = Bs[(n + g) * 36 + k8 + c];
                uint32_t b1 = Bs[(n + g) * 36 + k8 + c + 4];
#pragma unroll
                for (int im = 0; im < 2; im++)
                    mma8(acc[im][jn], af[im][0], af[im][1], af[im][2], af[im][3], b0, b1);
            }
        }
        __syncthreads();
    }
#pragma unroll
    for (int jn = 0; jn < 8; jn++) {
        int col = n0 + wn + jn * 8 + 2 * c;
        float bv0 = bias[col], bv1 = bias[col + 1];
#pragma unroll
        for (int im = 0; im < 2; im++) {
            int row = m0 + wm + im * 16 + g;
            float v00 = acc[im][jn][0] + bv0;
            float v01 = acc[im][jn][1] + bv1;
            float v10 = acc[im][jn][2] + bv0;
            float v11 = acc[im][jn][3] + bv1;
            if (EPI == 1) {
                v00 = 0.5f * v00 * (1.f + erff(v00 * 0.70710678118654752f));
                v01 = 0.5f * v01 * (1.f + erff(v01 * 0.70710678118654752f));
                v10 = 0.5f * v10 * (1.f + erff(v10 * 0.70710678118654752f));
                v11 = 0.5f * v11 * (1.f + erff(v11 * 0.70710678118654752f));
            }
            float2 r0 = {v00, v01}, r1 = {v10, v11};
            *(float2*)&C[(size_t)row * Nn + col] = r0;
            *(float2*)&C[(size_t)(row + 8) * Nn + col] = r1;
        }
    }
}

// ================= flash attention (online softmax, tf32 mma) ==============
// Per (b,h,q-tile of 64): 128 threads, 4 warps x 16 q-rows. Single pass over
// keys; S-tile in regs -> rescale -> P via per-warp smem -> PV accumulate.
// smem: Qs[64][68], Ks[64][68], Ps[64][68], Vs[64][72]  (~70.7 KB)
#define FL_SMEM ((64*68*3 + 64*72) * 4)

__global__ __launch_bounds__(128)
void flash_attn_kernel(const float* __restrict__ QKV, float* __restrict__ O) {
    extern __shared__ uint32_t fsm[];
    uint32_t* Qs = fsm;              // [64][68]
    uint32_t* Ks = Qs + 64 * 68;     // [64][68]
    uint32_t* Ps = Ks + 64 * 68;     // [64][68]
    uint32_t* Vs = Ps + 64 * 68;     // [64][72]

    const int bh = blockIdx.x;
    const int b = bh >> 3, h = bh & 7;
    const int q0 = blockIdx.y * 64;
    const int t = threadIdx.x;
    const int lane = t & 31, wid = t >> 5;
    const int g = lane >> 2, c = lane & 3;
    const int wm = wid * 16;
    const size_t qb = (size_t)b * NN * 1536 + h * 64;   // + n*1536 + d
    const float sc = 0.125f;

    // load Q tile [64][64] tf32
#pragma unroll
    for (int p = 0; p < 8; p++) {
        int idx = p * 128 + t;
        int r = idx >> 4, f4 = (idx & 15) * 4;
        float4 v = *(const float4*)&QKV[qb + (size_t)(q0 + r) * 1536 + f4];
        uint4 u = {f2tf32(v.x), f2tf32(v.y), f2tf32(v.z), f2tf32(v.w)};
        *(uint4*)&Qs[r * 68 + f4] = u;
    }

    float o[8][4];
#pragma unroll
    for (int nt = 0; nt < 8; nt++)
#pragma unroll
        for (int e = 0; e < 4; e++) o[nt][e] = 0.f;
    float M0 = -1e30f, M1 = -1e30f, l0 = 0.f, l1 = 0.f;

    for (int c0 = 0; c0 < NN; c0 += 64) {
        __syncthreads();   // prior-iter K/V reads done; also publishes Q (iter 0)
#pragma unroll
        for (int p = 0; p < 8; p++) {
            int idx = p * 128 + t;
            int r = idx >> 4, f4 = (idx & 15) * 4;
            float4 kv = *(const float4*)&QKV[qb + 512 + (size_t)(c0 + r) * 1536 + f4];
            uint4 uk = {f2tf32(kv.x), f2tf32(kv.y), f2tf32(kv.z), f2tf32(kv.w)};
            *(uint4*)&Ks[r * 68 + f4] = uk;
            float4 vv = *(const float4*)&QKV[qb + 1024 + (size_t)(c0 + r) * 1536 + f4];
            uint4 uv = {f2tf32(vv.x), f2tf32(vv.y), f2tf32(vv.z), f2tf32(vv.w)};
            *(uint4*)&Vs[r * 72 + f4] = uv;
        }
        __syncthreads();

        // ---- S = Q @ K^T (warp's 16 rows x 64 keys) ----
        float s[8][4];
#pragma unroll
        for (int nt = 0; nt < 8; nt++)
#pragma unroll
            for (int e = 0; e < 4; e++) s[nt][e] = 0.f;
#pragma unroll
        for (int k8 = 0; k8 < 8; k8++) {
            uint32_t a0 = Qs[(wm + g) * 68 + k8 * 8 + c];
            uint32_t a1 = Qs[(wm + g + 8) * 68 + k8 * 8 + c];
            uint32_t a2 = Qs[(wm + g) * 68 + k8 * 8 + c + 4];
            uint32_t a3 = Qs[(wm + g + 8) * 68 + k8 * 8 + c + 4];
#pragma unroll
            for (int nt = 0; nt < 8; nt++) {
                uint32_t b0 = Ks[(nt * 8 + g) * 68 + k8 * 8 + c];
                uint32_t b1 = Ks[(nt * 8 + g) * 68 + k8 * 8 + c + 4];
                mma8(s[nt], a0, a1, a2, a3, b0, b1);
            }
        }

        // ---- online softmax update ----
        float mx0 = -1e30f, mx1 = -1e30f;
#pragma unroll
        for (int nt = 0; nt < 8; nt++) {
            mx0 = fmaxf(mx0, fmaxf(s[nt][0], s[nt][1]));
            mx1 = fmaxf(mx1, fmaxf(s[nt][2], s[nt][3]));
        }
        mx0 *= sc; mx1 *= sc;
        mx0 = fmaxf(mx0, __shfl_xor_sync(0xFFFFFFFFu, mx0, 1));
        mx0 = fmaxf(mx0, __shfl_xor_sync(0xFFFFFFFFu, mx0, 2));
        mx1 = fmaxf(mx1, __shfl_xor_sync(0xFFFFFFFFu, mx1, 1));
        mx1 = fmaxf(mx1, __shfl_xor_sync(0xFFFFFFFFu, mx1, 2));
        float Mn0 = fmaxf(M0, mx0), Mn1 = fmaxf(M1, mx1);
        float es0 = __expf(M0 - Mn0), es1 = __expf(M1 - Mn1);
        M0 = Mn0; M1 = Mn1;
        float sum0 = 0.f, sum1 = 0.f;
#pragma unroll
        for (int nt = 0; nt < 8; nt++) {
            float p00 = __expf(sc * s[nt][0] - Mn0);
            float p01 = __expf(sc * s[nt][1] - Mn0);
            float p10 = __expf(sc * s[nt][2] - Mn1);
            float p11 = __expf(sc * s[nt][3] - Mn1);
            sum0 += p00 + p01; sum1 += p10 + p11;
            uint2 w0 = {f2tf32(p00), f2tf32(p01)};
            uint2 w1 = {f2tf32(p10), f2tf32(p11)};
            *(uint2*)&Ps[(wm + g) * 68 + nt * 8 + 2 * c] = w0;
            *(uint2*)&Ps[(wm + g + 8) * 68 + nt * 8 + 2 * c] = w1;
        }
        l0 = l0 * es0 + sum0;
        l1 = l1 * es1 + sum1;
#pragma unroll
        for (int nt = 0; nt < 8; nt++) {
            o[nt][0] *= es0; o[nt][1] *= es0;
            o[nt][2] *= es1; o[nt][3] *= es1;
        }
        __syncwarp();

        // ---- O += P @ V ----
#pragma unroll
        for (int k8 = 0; k8 < 8; k8++) {
            uint32_t a0 = Ps[(wm + g) * 68 + k8 * 8 + c];
            uint32_t a1 = Ps[(wm + g + 8) * 68 + k8 * 8 + c];
            uint32_t a2 = Ps[(wm + g) * 68 + k8 * 8 + c + 4];
            uint32_t a3 = Ps[(wm + g + 8) * 68 + k8 * 8 + c + 4];
#pragma unroll
            for (int nt = 0; nt < 8; nt++) {
                uint32_t b0 = Vs[(k8 * 8 + c) * 72 + nt * 8 + g];
                uint32_t b1 = Vs[(k8 * 8 + c + 4) * 72 + nt * 8 + g];
                mma8(o[nt], a0, a1, a2, a3, b0, b1);
            }
        }
    }

    // ---- finalize: row sums across c-lanes, normalize, store ----
    l0 += __shfl_xor_sync(0xFFFFFFFFu, l0, 1);
    l0 += __shfl_xor_sync(0xFFFFFFFFu, l0, 2);
    l1 += __shfl_xor_sync(0xFFFFFFFFu, l1, 1);
    l1 += __shfl_xor_sync(0xFFFFFFFFu, l1, 2);
    float iv0 = 1.f / l0, iv1 = 1.f / l1;
    const size_t ob = ((size_t)b * NN) * DD + h * DKK;
#pragma unroll
    for (int nt = 0; nt < 8; nt++) {
        int col = nt * 8 + 2 * c;
        float2 r0 = {o[nt][0] * iv0, o[nt][1] * iv0};
        float2 r1 = {o[nt][2] * iv1, o[nt][3] * iv1};
        *(float2*)&O[ob + (size_t)(q0 + wm + g) * DD + col] = r0;
        *(float2*)&O[ob + (size_t)(q0 + wm + g + 8) * DD + col] = r1;
    }
}

// ---------------- residual + LayerNorm over D=512 --------------------------
__global__ __launch_bounds__(128)
void add_ln_kernel(const float* __restrict__ X, const float* __restrict__ Y,
                   const float* __restrict__ g, const float* __restrict__ bt,
                   float* __restrict__ out) {
    __shared__ float sh[8];
    const int row = blockIdx.x;
    const int t = threadIdx.x;
    float4 x4 = *(const float4*)&X[(size_t)row * 512 + t * 4];
    float4 y4 = *(const float4*)&Y[(size_t)row * 512 + t * 4];
    float v[4] = {x4.x + y4.x, x4.y + y4.y, x4.z + y4.z, x4.w + y4.w};
    float s = v[0] + v[1] + v[2] + v[3];
    float s2 = v[0]*v[0] + v[1]*v[1] + v[2]*v[2] + v[3]*v[3];
#pragma unroll
    for (int off = 16; off; off >>= 1) {
        s  += __shfl_xor_sync(0xFFFFFFFFu, s, off);
        s2 += __shfl_xor_sync(0xFFFFFFFFu, s2, off);
    }
    if ((t & 31) == 0) { sh[t >> 5] = s; sh[4 + (t >> 5)] = s2; }
    __syncthreads();
    s  = sh[0] + sh[1] + sh[2] + sh[3];
    s2 = sh[4] + sh[5] + sh[6] + sh[7];
    float mean = s * (1.f / 512.f);
    float var  = s2 * (1.f / 512.f) - mean * mean;
    float rs = rsqrtf(var + 1e-5f);
    float4 g4 = *(const float4*)&g[t * 4];
    float4 b4 = *(const float4*)&bt[t * 4];
    float4 r;
    r.x = (v[0] - mean) * rs * g4.x + b4.x;
    r.y = (v[1] - mean) * rs * g4.y + b4.y;
    r.z = (v[2] - mean) * rs * g4.z + b4.z;
    r.w = (v[3] - mean) * rs * g4.w + b4.w;
    *(float4*)&out[(size_t)row * 512 + t * 4] = r;
}

// ---------------- gate finisher: LN(128) -> ReLU -> Linear(128,8) -> softmax
__global__ __launch_bounds__(128)
void gate_finish_kernel(const float* __restrict__ Hraw,
                        const float* __restrict__ lng, const float* __restrict__ lnb,
                        const float* __restrict__ Wg2, const float* __restrict__ bg2,
                        float* __restrict__ gates) {
    __shared__ float sh[8];
    __shared__ float sv[128];
    __shared__ float logits[8];
    const int row = blockIdx.x;
    const int t = threadIdx.x;
    float v = Hraw[(size_t)row * 128 + t];
    float s = v, s2 = v * v;
#pragma unroll
    for (int off = 16; off; off >>= 1) {
        s  += __shfl_xor_sync(0xFFFFFFFFu, s, off);
        s2 += __shfl_xor_sync(0xFFFFFFFFu, s2, off);
    }
    if ((t & 31) == 0) { sh[t >> 5] = s; sh[4 + (t >> 5)] = s2; }
    __syncthreads();
    s  = sh[0] + sh[1] + sh[2] + sh[3];
    s2 = sh[4] + sh[5] + sh[6] + sh[7];
    float mean = s * (1.f / 128.f);
    float var  = s2 * (1.f / 128.f) - mean * mean;
    float x = (v - mean) * rsqrtf(var + 1e-5f) * lng[t] + lnb[t];
    sv[t] = fmaxf(x, 0.f);
    __syncthreads();
    int w = t >> 5, lane = t & 31;
    for (int hh = w; hh < 8; hh += 4) {
        const float* wr = &Wg2[hh * 128];
        float p = sv[lane] * wr[lane] + sv[lane + 32] * wr[lane + 32]
                + sv[lane + 64] * wr[lane + 64] + sv[lane + 96] * wr[lane + 96];
#pragma unroll
        for (int off = 16; off; off >>= 1) p += __shfl_xor_sync(0xFFFFFFFFu, p, off);
        if (lane == 0) logits[hh] = p + bg2[hh];
    }
    __syncthreads();
    if (t == 0) {
        float mx = -1e30f;
#pragma unroll
        for (int hh = 0; hh < 8; hh++) mx = fmaxf(mx, logits[hh]);
        float e[8], sum = 0.f;
#pragma unroll
        for (int hh = 0; hh < 8; hh++) { e[hh] = __expf(logits[hh] - mx); sum += e[hh]; }
        float isum = 1.f / sum;
#pragma unroll
        for (int hh = 0; hh < 8; hh++) gates[(size_t)row * 8 + hh] = e[hh] * isum;
    }
}

// ---------------- fused = sum_h cma[b, h*C + c, n] * gates[b,n,h] ----------
__global__ __launch_bounds__(256)
void fused_kernel(const float* __restrict__ cma, const float* __restrict__ gates,
                  float* __restrict__ out) {
    int idx = blockIdx.x * 256 + threadIdx.x;
    int n = idx & 511;
    int c = (idx >> 9) & 511;
    int b = idx >> 18;
    const float* gp = &gates[((size_t)b * 512 + n) * 8];
    const float* cp = &cma[(size_t)b * HC * NN + (size_t)c * NN + n];
    float acc = 0.f;
#pragma unroll
    for (int hh = 0; hh < 8; hh++)
        acc += cp[(size_t)hh * CC * NN] * gp[hh];
    out[idx] = acc;
}

// ---------------- host launcher --------------------------------------------
extern "C" void kernel_launch(void* const* d_in, const int* in_sizes, int n_in,
                              void* d_out, int out_size) {
    const float* q    = (const float*)d_in[0];
    const float* k    = (const float*)d_in[1];
    const float* v    = (const float*)d_in[2];
    const float* cma  = (const float*)d_in[3];
    const float* Wq   = (const float*)d_in[4];
    const float* bq   = (const float*)d_in[5];
    const float* Wk   = (const float*)d_in[6];
    const float* bk   = (const float*)d_in[7];
    const float* Wv   = (const float*)d_in[8];
    const float* bv   = (const float*)d_in[9];
    const float* Wo   = (const float*)d_in[10];
    const float* bo   = (const float*)d_in[11];
    const float* ln1g = (const float*)d_in[12];
    const float* ln1b = (const float*)d_in[13];
    const float* ln2g = (const float*)d_in[14];
    const float* ln2b = (const float*)d_in[15];
    const float* W1   = (const float*)d_in[16];
    const float* b1   = (const float*)d_in[17];
    const float* W2   = (const float*)d_in[18];
    const float* b2   = (const float*)d_in[19];
    const float* Wg1  = (const float*)d_in[20];
    const float* bg1  = (const float*)d_in[21];
    const float* lngg = (const float*)d_in[22];
    const float* lngb = (const float*)d_in[23];
    const float* Wg2  = (const float*)d_in[24];
    const float* bg2  = (const float*)d_in[25];

    float *p_qkv, *p_att, *p_o, *p_x, *p_ffh, *p_ff2, *p_ghr, *p_gates;
    float *p_wqkv, *p_bqkv, *p_wo, *p_w1, *p_w2, *p_wg1;
    cudaGetSymbolAddress((void**)&p_qkv, g_qkv);
    cudaGetSymbolAddress((void**)&p_att, g_att);
    cudaGetSymbolAddress((void**)&p_o,   g_o);
    cudaGetSymbolAddress((void**)&p_x,   g_x);
    cudaGetSymbolAddress((void**)&p_ffh, g_ffh);
    cudaGetSymbolAddress((void**)&p_ff2, g_ff2);
    cudaGetSymbolAddress((void**)&p_ghr, g_ghr);
    cudaGetSymbolAddress((void**)&p_gates, g_gates);
    cudaGetSymbolAddress((void**)&p_wqkv, g_wqkv);
    cudaGetSymbolAddress((void**)&p_bqkv, g_bqkv);
    cudaGetSymbolAddress((void**)&p_wo,  g_wo);
    cudaGetSymbolAddress((void**)&p_w1,  g_w1);
    cudaGetSymbolAddress((void**)&p_w2,  g_w2);
    cudaGetSymbolAddress((void**)&p_wg1, g_wg1);

    constexpr int SM_N = 3 * (128 * 36 + 128 * 36) * 4;   // 110592
    constexpr int SM_T = 3 * (32 * 132 + 128 * 36) * 4;   // 105984
    cudaFuncSetAttribute(flash_attn_kernel, cudaFuncAttributeMaxDynamicSharedMemorySize, FL_SMEM);
    cudaFuncSetAttribute(gemm_mma<0,false,true>,  cudaFuncAttributeMaxDynamicSharedMemorySize, SM_N);
    cudaFuncSetAttribute(gemm_mma<0,false,false>, cudaFuncAttributeMaxDynamicSharedMemorySize, SM_N);
    cudaFuncSetAttribute(gemm_mma<1,false,false>, cudaFuncAttributeMaxDynamicSharedMemorySize, SM_N);
    cudaFuncSetAttribute(gemm_mma<0,true,false>,  cudaFuncAttributeMaxDynamicSharedMemorySize, SM_T);

    float* out_enc   = (float*)d_out;                       // [B,N,D]
    float* out_fused = (float*)d_out + (size_t)MM * DD;     // [B,C,N]

    // pack / pre-round weights (tf32 bits)
    pack_qkv_w_kernel<<<3*DD*DD/1024, 256>>>(Wq, Wk, Wv, p_wqkv);
    pack_qkv_b_kernel<<<6, 256>>>(bq, bk, bv, p_bqkv);
    cvt_tf32_kernel<<<DD*DD/1024, 256>>>(Wo, p_wo, DD*DD);
    cvt_tf32_kernel<<<DFF*DD/1024, 256>>>(W1, p_w1, DFF*DD);
    cvt_tf32_kernel<<<DD*DFF/1024, 256>>>(W2, p_w2, DD*DFF);
    cvt_tf32_kernel<<<GHH*HC/1024, 256>>>(Wg1, p_wg1, GHH*HC);

    // QKV projections (cross-attention!): z=0 -> q@Wq, z=1 -> k@Wk, z=2 -> v@Wv
    // packed output g_qkv [8192][1536]; columns z*512..z*512+511
    gemm_mma<0,false,true><<<dim3(MM/128, 4, 3), 256, SM_N>>>(
        q, p_wqkv, p_bqkv, p_qkv, MM, DD, 1536, k, v);
    // flash attention (packed QKV input)
    flash_attn_kernel<<<dim3(BB*HH, NN/64), 128, FL_SMEM>>>(p_qkv, p_att);
    // output projection + LN1
    gemm_mma<0,false,false><<<dim3(MM/128, DD/128), 256, SM_N>>>(
        p_att, p_wo, bo, p_o, MM, DD, DD, nullptr, nullptr);
    add_ln_kernel<<<MM, 128>>>(q, p_o, ln1g, ln1b, p_x);
    // FFN
    gemm_mma<1,false,false><<<dim3(MM/128, DFF/128), 256, SM_N>>>(
        p_x, p_w1, b1, p_ffh, MM, DD, DFF, nullptr, nullptr);
    gemm_mma<0,false,false><<<dim3(MM/128, DD/128), 256, SM_N>>>(
        p_ffh, p_w2, b2, p_ff2, MM, DFF, DD, nullptr, nullptr);
    add_ln_kernel<<<MM, 128>>>(p_x, p_ff2, ln2g, ln2b, out_enc);
    // gate MLP (strided A from cma) + finisher
    gemm_mma<0,true,false><<<dim3(MM/128, GHH/128), 256, SM_T>>>(
        cma, p_wg1, bg1, p_ghr, MM, HC, GHH, nullptr, nullptr);
    gate_finish_kernel<<<MM, 128>>>(p_ghr, lngg, lngb, Wg2, bg2, p_gates);
    // gated fusion
    fused_kernel<<<(BB*CC*NN)/256, 256>>>(cma, p_gates, out_fused);
}

// round 15
// speedup vs baseline: 3.7544x; 1.2424x over previous
#include <cuda_runtime.h>
#include <cuda_fp16.h>
#include <cstdint>
#include <cmath>

// Problem constants
#define BB 16
#define NN 512
#define DD 512
#define HH 8
#define DKK 64
#define DFF 2048
#define GHH 128
#define MM (BB*NN)          // 8192
#define HC (HH*DD)          // 4096
#define CC 512              // HC / H

// ---------------- scratch (device globals; no allocation allowed) ----------
__device__ float  g_qkv [MM*3*DD];    // packed QKV (fp32, read by flash)
__device__ __half g_att16[MM*DD];     // attention out (fp16, feeds Wo)
__device__ float  g_o   [MM*DD];
__device__ float  g_x   [MM*DD];
__device__ __half g_x16 [MM*DD];      // fp16 copy of x (feeds FFN1)
__device__ __half g_ffh16[MM*DFF];    // GELU out (fp16, feeds FFN2)
__device__ float  g_ff2 [MM*DD];
__device__ float  g_ghr [MM*GHH];
__device__ float  g_gates[MM*HH];
// fp16 activations of inputs
__device__ __half g_q16 [MM*DD];
__device__ __half g_k16 [MM*DD];
__device__ __half g_v16 [MM*DD];
// pre-converted weights
__device__ __half g_wqkv16[3*DD*DD];  // [1536][512] rows: Wq|Wk|Wv (fp16)
__device__ float  g_bqkv[3*DD];
__device__ __half g_wo16[DD*DD];
__device__ __half g_w116[DFF*DD];
__device__ __half g_w216[DD*DFF];
__device__ float  g_wg1 [GHH*HC];     // tf32-rounded (gate GEMM stays tf32)

__device__ __forceinline__ uint32_t f2tf32(float x) {
    uint32_t r;
    asm("cvt.rna.tf32.f32 %0, %1;" : "=r"(r) : "f"(x));
    return r;
}
__device__ __forceinline__ void mma8(float* d, uint32_t a0, uint32_t a1,
                                     uint32_t a2, uint32_t a3,
                                     uint32_t b0, uint32_t b1) {
    asm volatile("mma.sync.aligned.m16n8k8.row.col.f32.tf32.tf32.f32 "
        "{%0,%1,%2,%3}, {%4,%5,%6,%7}, {%8,%9}, {%0,%1,%2,%3};"
        : "+f"(d[0]), "+f"(d[1]), "+f"(d[2]), "+f"(d[3])
        : "r"(a0), "r"(a1), "r"(a2), "r"(a3), "r"(b0), "r"(b1));
}
__device__ __forceinline__ void mma16(float* d, uint32_t a0, uint32_t a1,
                                      uint32_t a2, uint32_t a3,
                                      uint32_t b0, uint32_t b1) {
    asm volatile("mma.sync.aligned.m16n8k16.row.col.f32.f16.f16.f32 "
        "{%0,%1,%2,%3}, {%4,%5,%6,%7}, {%8,%9}, {%0,%1,%2,%3};"
        : "+f"(d[0]), "+f"(d[1]), "+f"(d[2]), "+f"(d[3])
        : "r"(a0), "r"(a1), "r"(a2), "r"(a3), "r"(b0), "r"(b1));
}
__device__ __forceinline__ uint32_t smem_u32(const void* p) {
    return (uint32_t)__cvta_generic_to_shared(p);
}
__device__ __forceinline__ void cp16(uint32_t dst, const void* src) {
    asm volatile("cp.async.cg.shared.global [%0], [%1], 16;" :: "r"(dst), "l"(src));
}

// ---------------- weight / activation pre-conversion -----------------------
__global__ __launch_bounds__(256)
void cvt_tf32_kernel(const float* __restrict__ src, float* __restrict__ dst, int n) {
    int i = (blockIdx.x * 256 + threadIdx.x) * 4;
    if (i < n) {
        float4 v = *(const float4*)&src[i];
        uint4 u = {f2tf32(v.x), f2tf32(v.y), f2tf32(v.z), f2tf32(v.w)};
        *(uint4*)&dst[i] = u;
    }
}
__global__ __launch_bounds__(256)
void cvt_f16_kernel(const float* __restrict__ src, __half* __restrict__ dst, int n) {
    int i = (blockIdx.x * 256 + threadIdx.x) * 8;
    if (i < n) {
        float4 a = *(const float4*)&src[i];
        float4 b = *(const float4*)&src[i + 4];
        __half2 h0 = __floats2half2_rn(a.x, a.y);
        __half2 h1 = __floats2half2_rn(a.z, a.w);
        __half2 h2 = __floats2half2_rn(b.x, b.y);
        __half2 h3 = __floats2half2_rn(b.z, b.w);
        uint4 u = {*(uint32_t*)&h0, *(uint32_t*)&h1, *(uint32_t*)&h2, *(uint32_t*)&h3};
        *(uint4*)&dst[i] = u;
    }
}
__global__ __launch_bounds__(256)
void pack_qkv_w16_kernel(const float* __restrict__ Wq, const float* __restrict__ Wk,
                         const float* __restrict__ Wv, __half* __restrict__ dst) {
    int i = (blockIdx.x * 256 + threadIdx.x) * 8;   // over 1536*512
    int row = i >> 9, col = i & 511;
    const float* src = (row < 512) ? &Wq[(size_t)row * 512 + col]
                     : (row < 1024) ? &Wk[(size_t)(row - 512) * 512 + col]
                                    : &Wv[(size_t)(row - 1024) * 512 + col];
    float4 a = *(const float4*)&src[0];
    float4 b = *(const float4*)&src[4];
    __half2 h0 = __floats2half2_rn(a.x, a.y);
    __half2 h1 = __floats2half2_rn(a.z, a.w);
    __half2 h2 = __floats2half2_rn(b.x, b.y);
    __half2 h3 = __floats2half2_rn(b.z, b.w);
    uint4 u = {*(uint32_t*)&h0, *(uint32_t*)&h1, *(uint32_t*)&h2, *(uint32_t*)&h3};
    *(uint4*)&dst[i] = u;
}
__global__ __launch_bounds__(256)
void pack_qkv_b_kernel(const float* __restrict__ bq, const float* __restrict__ bk,
                       const float* __restrict__ bv, float* __restrict__ dst) {
    int i = blockIdx.x * 256 + threadIdx.x;
    dst[i] = (i < 512) ? bq[i] : (i < 1024) ? bk[i - 512] : bv[i - 1024];
}

// ================= fp16 mma.sync GEMM: C = A @ W^T + bias =================
// CTA 128x128, chunk = 32 halves, 3-stage cp.async, 256 thr = 8 warps (4Mx2N).
// smem rows: 40 halves (80B) stride -> conflict-free fragment LDS.32.
// FUSE3: blockIdx.z picks A from {A,A1,A2}, n0 += z*512 (packed QKV).
#define HA_STG32 (2 * 128 * 20)   // A+B stage size in u32
#define HSMEM (3 * HA_STG32 * 4)  // 61440 B

__device__ __forceinline__ void issue_stage_h(
    const __half* __restrict__ A, const __half* __restrict__ W,
    int K, int m0, int n0, int k0, int t, uint32_t sA, uint32_t sB) {
#pragma unroll
    for (int p = 0; p < 2; p++) {
        int idx = p * 256 + t;
        int row = idx >> 2, f = idx & 3;
        cp16(sA + (uint32_t)(row * 80 + f * 16),
             &A[(size_t)(m0 + row) * K + k0 + f * 8]);
        cp16(sB + (uint32_t)(row * 80 + f * 16),
             &W[(size_t)(n0 + row) * K + k0 + f * 8]);
    }
    asm volatile("cp.async.commit_group;" ::: "memory");
}

template<int EPI, bool OUT16, bool FUSE3>
__global__ __launch_bounds__(256, 2)
void gemm_h(const __half* __restrict__ A, const __half* __restrict__ W,
            const float* __restrict__ bias, void* __restrict__ Cv,
            int M, int K, int Nn,
            const __half* __restrict__ A1, const __half* __restrict__ A2) {
    extern __shared__ uint32_t hsm[];
    const uint32_t sbase = smem_u32(hsm);
    const int t = threadIdx.x;
    const int lane = t & 31, wid = t >> 5;
    const int wm = (wid >> 1) * 32;
    const int wn = (wid & 1) * 64;
    const int m0 = blockIdx.x * 128;
    int n0 = blockIdx.y * 128;
    const __half* Ax = A;
    if (FUSE3) {
        const int z = blockIdx.z;
        Ax = (z == 0) ? A : (z == 1) ? A1 : A2;
        n0 += z * 512;
    }
    const int g = lane >> 2, c = lane & 3;
    const int NSTEP = K / 32;

    float acc[2][8][4];
#pragma unroll
    for (int im = 0; im < 2; im++)
#pragma unroll
        for (int jn = 0; jn < 8; jn++)
#pragma unroll
            for (int e = 0; e < 4; e++) acc[im][jn][e] = 0.f;

    issue_stage_h(Ax, W, K, m0, n0, 0,  t, sbase, sbase + 128 * 80);
    issue_stage_h(Ax, W, K, m0, n0, 32, t, sbase + HA_STG32 * 4, sbase + HA_STG32 * 4 + 128 * 80);

    for (int s = 0; s < NSTEP; s++) {
        if (s == NSTEP - 1)
            asm volatile("cp.async.wait_group 0;" ::: "memory");
        else
            asm volatile("cp.async.wait_group 1;" ::: "memory");
        __syncthreads();
        if (s + 2 < NSTEP) {
            int st = (s + 2) % 3;
            issue_stage_h(Ax, W, K, m0, n0, (s + 2) * 32, t,
                          sbase + (uint32_t)(st * HA_STG32) * 4,
                          sbase + (uint32_t)(st * HA_STG32) * 4 + 128 * 80);
        }
        const uint32_t* As = hsm + (s % 3) * HA_STG32;   // [128][20] u32
        const uint32_t* Bs = As + 128 * 20;
#pragma unroll
        for (int kk8 = 0; kk8 < 16; kk8 += 8) {          // 2 x k16 steps
            uint32_t af[2][4];
#pragma unroll
            for (int im = 0; im < 2; im++) {
                const int m = wm + im * 16;
                af[im][0] = As[(m + g) * 20 + kk8 + c];
                af[im][1] = As[(m + g + 8) * 20 + kk8 + c];
                af[im][2] = As[(m + g) * 20 + kk8 + c + 4];
                af[im][3] = As[(m + g + 8) * 20 + kk8 + c + 4];
            }
#pragma unroll
            for (int jn = 0; jn < 8; jn++) {
                const int n = wn + jn * 8;
                uint32_t b0 = Bs[(n + g) * 20 + kk8 + c];
                uint32_t b1 = Bs[(n + g) * 20 + kk8 + c + 4];
#pragma unroll
                for (int im = 0; im < 2; im++)
                    mma16(acc[im][jn], af[im][0], af[im][1], af[im][2], af[im][3], b0, b1);
            }
        }
        __syncthreads();
    }
    // ---- epilogue ----
#pragma unroll
    for (int jn = 0; jn < 8; jn++) {
        int col = n0 + wn + jn * 8 + 2 * c;
        float bv0 = bias[col], bv1 = bias[col + 1];
#pragma unroll
        for (int im = 0; im < 2; im++) {
            int row = m0 + wm + im * 16 + g;
            float v00 = acc[im][jn][0] + bv0;
            float v01 = acc[im][jn][1] + bv1;
            float v10 = acc[im][jn][2] + bv0;
            float v11 = acc[im][jn][3] + bv1;
            if (EPI == 1) {
                v00 = 0.5f * v00 * (1.f + erff(v00 * 0.70710678118654752f));
                v01 = 0.5f * v01 * (1.f + erff(v01 * 0.70710678118654752f));
                v10 = 0.5f * v10 * (1.f + erff(v10 * 0.70710678118654752f));
                v11 = 0.5f * v11 * (1.f + erff(v11 * 0.70710678118654752f));
            }
            if (OUT16) {
                __half* C = (__half*)Cv;
                __half2 h0 = __floats2half2_rn(v00, v01);
                __half2 h1 = __floats2half2_rn(v10, v11);
                *(__half2*)&C[(size_t)row * Nn + col] = h0;
                *(__half2*)&C[(size_t)(row + 8) * Nn + col] = h1;
            } else {
                float* C = (float*)Cv;
                float2 r0 = {v00, v01}, r1 = {v10, v11};
                *(float2*)&C[(size_t)row * Nn + col] = r0;
                *(float2*)&C[(size_t)(row + 8) * Nn + col] = r1;
            }
        }
    }
}

// ================= tf32 GEMM for the gate MLP (strided A from cma) =========
#define GT_ASZ (32 * 132)
#define GT_BSZ (128 * 36)
#define GT_STG (GT_ASZ + GT_BSZ)
#define GT_SMEM (3 * GT_STG * 4)

__device__ __forceinline__ void issue_stage_g(
    const float* __restrict__ A, const float* __restrict__ W,
    int m0, int k0, int t, uint32_t sA, uint32_t sB) {
    const int b = m0 >> 9, nb = m0 & 511;
#pragma unroll
    for (int p = 0; p < 4; p++) {
        int idx = p * 256 + t;
        int kc = idx >> 5, nf = idx & 31;
        cp16(sA + (uint32_t)(kc * 132 + nf * 4) * 4,
             &A[(size_t)b * HC * 512 + (size_t)(k0 + kc) * 512 + nb + nf * 4]);
    }
#pragma unroll
    for (int p = 0; p < 4; p++) {
        int idx = p * 256 + t;
        int row = idx >> 3, f4 = idx & 7;
        cp16(sB + (uint32_t)(row * 36 + f4 * 4) * 4,
             &W[(size_t)row * HC + k0 + f4 * 4]);
    }
    asm volatile("cp.async.commit_group;" ::: "memory");
}

__global__ __launch_bounds__(256, 2)
void gemm_gate(const float* __restrict__ A, const float* __restrict__ W,
               const float* __restrict__ bias, float* __restrict__ C) {
    extern __shared__ float gsm[];
    const uint32_t sbase = smem_u32(gsm);
    const int t = threadIdx.x;
    const int lane = t & 31, wid = t >> 5;
    const int wm = (wid >> 1) * 32;
    const int wn = (wid & 1) * 64;
    const int m0 = blockIdx.x * 128;
    const int g = lane >> 2, c = lane & 3;
    const int NSTEP = HC / 32;

    float acc[2][8][4];
#pragma unroll
    for (int im = 0; im < 2; im++)
#pragma unroll
        for (int jn = 0; jn < 8; jn++)
#pragma unroll
            for (int e = 0; e < 4; e++) acc[im][jn][e] = 0.f;

    issue_stage_g(A, W, m0, 0,  t, sbase, sbase + GT_ASZ * 4);
    issue_stage_g(A, W, m0, 32, t, sbase + GT_STG * 4, sbase + (GT_STG + GT_ASZ) * 4);

    for (int s = 0; s < NSTEP; s++) {
        if (s == NSTEP - 1)
            asm volatile("cp.async.wait_group 0;" ::: "memory");
        else
            asm volatile("cp.async.wait_group 1;" ::: "memory");
        __syncthreads();
        if (s + 2 < NSTEP) {
            int st = (s + 2) % 3;
            issue_stage_g(A, W, m0, (s + 2) * 32, t,
                          sbase + (uint32_t)(st * GT_STG) * 4,
                          sbase + (uint32_t)(st * GT_STG + GT_ASZ) * 4);
        }
        const uint32_t* As = (const uint32_t*)(gsm + (s % 3) * GT_STG);
        const uint32_t* Bs = As + GT_ASZ;
#pragma unroll
        for (int ks = 0; ks < 4; ks++) {
            const int k8 = ks * 8;
            uint32_t af[2][4];
#pragma unroll
            for (int im = 0; im < 2; im++) {
                const int m = wm + im * 16;
                af[im][0] = f2tf32(__uint_as_float(As[(k8 + c) * 132 + m + g]));
                af[im][1] = f2tf32(__uint_as_float(As[(k8 + c) * 132 + m + g + 8]));
                af[im][2] = f2tf32(__uint_as_float(As[(k8 + c + 4) * 132 + m + g]));
                af[im][3] = f2tf32(__uint_as_float(As[(k8 + c + 4) * 132 + m + g + 8]));
            }
#pragma unroll
            for (int jn = 0; jn < 8; jn++) {
                const int n = wn + jn * 8;
                uint32_t b0 = Bs[(n + g) * 36 + k8 + c];
                uint32_t b1 = Bs[(n + g) * 36 + k8 + c + 4];
#pragma unroll
                for (int im = 0; im < 2; im++)
                    mma8(acc[im][jn], af[im][0], af[im][1], af[im][2], af[im][3], b0, b1);
            }
        }
        __syncthreads();
    }
#pragma unroll
    for (int jn = 0; jn < 8; jn++) {
        int col = wn + jn * 8 + 2 * c;
        float bv0 = bias[col], bv1 = bias[col + 1];
#pragma unroll
        for (int im = 0; im < 2; im++) {
            int row = m0 + wm + im * 16 + g;
            float2 r0 = {acc[im][jn][0] + bv0, acc[im][jn][1] + bv1};
            float2 r1 = {acc[im][jn][2] + bv0, acc[im][jn][3] + bv1};
            *(float2*)&C[(size_t)row * GHH + col] = r0;
            *(float2*)&C[(size_t)(row + 8) * GHH + col] = r1;
        }
    }
}

// ================= flash attention (online softmax, tf32 mma) ==============
#define FL_SMEM ((64*68*3 + 64*72) * 4)

__global__ __launch_bounds__(128)
void flash_attn_kernel(const float* __restrict__ QKV, __half* __restrict__ O16) {
    extern __shared__ uint32_t fsm[];
    uint32_t* Qs = fsm;              // [64][68]
    uint32_t* Ks = Qs + 64 * 68;     // [64][68]
    uint32_t* Ps = Ks + 64 * 68;     // [64][68]
    uint32_t* Vs = Ps + 64 * 68;     // [64][72]

    const int bh = blockIdx.x;
    const int b = bh >> 3, h = bh & 7;
    const int q0 = blockIdx.y * 64;
    const int t = threadIdx.x;
    const int lane = t & 31, wid = t >> 5;
    const int g = lane >> 2, c = lane & 3;
    const int wm = wid * 16;
    const size_t qb = (size_t)b * NN * 1536 + h * 64;
    const float sc = 0.125f;

#pragma unroll
    for (int p = 0; p < 8; p++) {
        int idx = p * 128 + t;
        int r = idx >> 4, f4 = (idx & 15) * 4;
        float4 v = *(const float4*)&QKV[qb + (size_t)(q0 + r) * 1536 + f4];
        uint4 u = {f2tf32(v.x), f2tf32(v.y), f2tf32(v.z), f2tf32(v.w)};
        *(uint4*)&Qs[r * 68 + f4] = u;
    }

    float o[8][4];
#pragma unroll
    for (int nt = 0; nt < 8; nt++)
#pragma unroll
        for (int e = 0; e < 4; e++) o[nt][e] = 0.f;
    float M0 = -1e30f, M1 = -1e30f, l0 = 0.f, l1 = 0.f;

    for (int c0 = 0; c0 < NN; c0 += 64) {
        __syncthreads();
#pragma unroll
        for (int p = 0; p < 8; p++) {
            int idx = p * 128 + t;
            int r = idx >> 4, f4 = (idx & 15) * 4;
            float4 kv = *(const float4*)&QKV[qb + 512 + (size_t)(c0 + r) * 1536 + f4];
            uint4 uk = {f2tf32(kv.x), f2tf32(kv.y), f2tf32(kv.z), f2tf32(kv.w)};
            *(uint4*)&Ks[r * 68 + f4] = uk;
            float4 vv = *(const float4*)&QKV[qb + 1024 + (size_t)(c0 + r) * 1536 + f4];
            uint4 uv = {f2tf32(vv.x), f2tf32(vv.y), f2tf32(vv.z), f2tf32(vv.w)};
            *(uint4*)&Vs[r * 72 + f4] = uv;
        }
        __syncthreads();

        float s[8][4];
#pragma unroll
        for (int nt = 0; nt < 8; nt++)
#pragma unroll
            for (int e = 0; e < 4; e++) s[nt][e] = 0.f;
#pragma unroll
        for (int k8 = 0; k8 < 8; k8++) {
            uint32_t a0 = Qs[(wm + g) * 68 + k8 * 8 + c];
            uint32_t a1 = Qs[(wm + g + 8) * 68 + k8 * 8 + c];
            uint32_t a2 = Qs[(wm + g) * 68 + k8 * 8 + c + 4];
            uint32_t a3 = Qs[(wm + g + 8) * 68 + k8 * 8 + c + 4];
#pragma unroll
            for (int nt = 0; nt < 8; nt++) {
                uint32_t b0 = Ks[(nt * 8 + g) * 68 + k8 * 8 + c];
                uint32_t b1 = Ks[(nt * 8 + g) * 68 + k8 * 8 + c + 4];
                mma8(s[nt], a0, a1, a2, a3, b0, b1);
            }
        }

        float mx0 = -1e30f, mx1 = -1e30f;
#pragma unroll
        for (int nt = 0; nt < 8; nt++) {
            mx0 = fmaxf(mx0, fmaxf(s[nt][0], s[nt][1]));
            mx1 = fmaxf(mx1, fmaxf(s[nt][2], s[nt][3]));
        }
        mx0 *= sc; mx1 *= sc;
        mx0 = fmaxf(mx0, __shfl_xor_sync(0xFFFFFFFFu, mx0, 1));
        mx0 = fmaxf(mx0, __shfl_xor_sync(0xFFFFFFFFu, mx0, 2));
        mx1 = fmaxf(mx1, __shfl_xor_sync(0xFFFFFFFFu, mx1, 1));
        mx1 = fmaxf(mx1, __shfl_xor_sync(0xFFFFFFFFu, mx1, 2));
        float Mn0 = fmaxf(M0, mx0), Mn1 = fmaxf(M1, mx1);
        float es0 = __expf(M0 - Mn0), es1 = __expf(M1 - Mn1);
        M0 = Mn0; M1 = Mn1;
        float sum0 = 0.f, sum1 = 0.f;
#pragma unroll
        for (int nt = 0; nt < 8; nt++) {
            float p00 = __expf(sc * s[nt][0] - Mn0);
            float p01 = __expf(sc * s[nt][1] - Mn0);
            float p10 = __expf(sc * s[nt][2] - Mn1);
            float p11 = __expf(sc * s[nt][3] - Mn1);
            sum0 += p00 + p01; sum1 += p10 + p11;
            uint2 w0 = {f2tf32(p00), f2tf32(p01)};
            uint2 w1 = {f2tf32(p10), f2tf32(p11)};
            *(uint2*)&Ps[(wm + g) * 68 + nt * 8 + 2 * c] = w0;
            *(uint2*)&Ps[(wm + g + 8) * 68 + nt * 8 + 2 * c] = w1;
        }
        l0 = l0 * es0 + sum0;
        l1 = l1 * es1 + sum1;
#pragma unroll
        for (int nt = 0; nt < 8; nt++) {
            o[nt][0] *= es0; o[nt][1] *= es0;
            o[nt][2] *= es1; o[nt][3] *= es1;
        }
        __syncwarp();

#pragma unroll
        for (int k8 = 0; k8 < 8; k8++) {
            uint32_t a0 = Ps[(wm + g) * 68 + k8 * 8 + c];
            uint32_t a1 = Ps[(wm + g + 8) * 68 + k8 * 8 + c];
            uint32_t a2 = Ps[(wm + g) * 68 + k8 * 8 + c + 4];
            uint32_t a3 = Ps[(wm + g + 8) * 68 + k8 * 8 + c + 4];
#pragma unroll
            for (int nt = 0; nt < 8; nt++) {
                uint32_t b0 = Vs[(k8 * 8 + c) * 72 + nt * 8 + g];
                uint32_t b1 = Vs[(k8 * 8 + c + 4) * 72 + nt * 8 + g];
                mma8(o[nt], a0, a1, a2, a3, b0, b1);
            }
        }
    }

    l0 += __shfl_xor_sync(0xFFFFFFFFu, l0, 1);
    l0 += __shfl_xor_sync(0xFFFFFFFFu, l0, 2);
    l1 += __shfl_xor_sync(0xFFFFFFFFu, l1, 1);
    l1 += __shfl_xor_sync(0xFFFFFFFFu, l1, 2);
    float iv0 = 1.f / l0, iv1 = 1.f / l1;
    const size_t ob = ((size_t)b * NN) * DD + h * DKK;
#pragma unroll
    for (int nt = 0; nt < 8; nt++) {
        int col = nt * 8 + 2 * c;
        __half2 r0 = __floats2half2_rn(o[nt][0] * iv0, o[nt][1] * iv0);
        __half2 r1 = __floats2half2_rn(o[nt][2] * iv1, o[nt][3] * iv1);
        *(__half2*)&O16[ob + (size_t)(q0 + wm + g) * DD + col] = r0;
        *(__half2*)&O16[ob + (size_t)(q0 + wm + g + 8) * DD + col] = r1;
    }
}

// ---------------- residual + LayerNorm (optional fp16 copy) ----------------
__global__ __launch_bounds__(128)
void add_ln_kernel(const float* __restrict__ X, const float* __restrict__ Y,
                   const float* __restrict__ g, const float* __restrict__ bt,
                   float* __restrict__ out, __half* __restrict__ out16) {
    __shared__ float sh[8];
    const int row = blockIdx.x;
    const int t = threadIdx.x;
    float4 x4 = *(const float4*)&X[(size_t)row * 512 + t * 4];
    float4 y4 = *(const float4*)&Y[(size_t)row * 512 + t * 4];
    float v[4] = {x4.x + y4.x, x4.y + y4.y, x4.z + y4.z, x4.w + y4.w};
    float s = v[0] + v[1] + v[2] + v[3];
    float s2 = v[0]*v[0] + v[1]*v[1] + v[2]*v[2] + v[3]*v[3];
#pragma unroll
    for (int off = 16; off; off >>= 1) {
        s  += __shfl_xor_sync(0xFFFFFFFFu, s, off);
        s2 += __shfl_xor_sync(0xFFFFFFFFu, s2, off);
    }
    if ((t & 31) == 0) { sh[t >> 5] = s; sh[4 + (t >> 5)] = s2; }
    __syncthreads();
    s  = sh[0] + sh[1] + sh[2] + sh[3];
    s2 = sh[4] + sh[5] + sh[6] + sh[7];
    float mean = s * (1.f / 512.f);
    float var  = s2 * (1.f / 512.f) - mean * mean;
    float rs = rsqrtf(var + 1e-5f);
    float4 g4 = *(const float4*)&g[t * 4];
    float4 b4 = *(const float4*)&bt[t * 4];
    float4 r;
    r.x = (v[0] - mean) * rs * g4.x + b4.x;
    r.y = (v[1] - mean) * rs * g4.y + b4.y;
    r.z = (v[2] - mean) * rs * g4.z + b4.z;
    r.w = (v[3] - mean) * rs * g4.w + b4.w;
    *(float4*)&out[(size_t)row * 512 + t * 4] = r;
    if (out16) {
        __half2 h0 = __floats2half2_rn(r.x, r.y);
        __half2 h1 = __floats2half2_rn(r.z, r.w);
        *(__half2*)&out16[(size_t)row * 512 + t * 4] = h0;
        *(__half2*)&out16[(size_t)row * 512 + t * 4 + 2] = h1;
    }
}

// ---------------- gate finisher: LN(128) -> ReLU -> Linear(128,8) -> softmax
__global__ __launch_bounds__(128)
void gate_finish_kernel(const float* __restrict__ Hraw,
                        const float* __restrict__ lng, const float* __restrict__ lnb,
                        const float* __restrict__ Wg2, const float* __restrict__ bg2,
                        float* __restrict__ gates) {
    __shared__ float sh[8];
    __shared__ float sv[128];
    __shared__ float logits[8];
    const int row = blockIdx.x;
    const int t = threadIdx.x;
    float v = Hraw[(size_t)row * 128 + t];
    float s = v, s2 = v * v;
#pragma unroll
    for (int off = 16; off; off >>= 1) {
        s  += __shfl_xor_sync(0xFFFFFFFFu, s, off);
        s2 += __shfl_xor_sync(0xFFFFFFFFu, s2, off);
    }
    if ((t & 31) == 0) { sh[t >> 5] = s; sh[4 + (t >> 5)] = s2; }
    __syncthreads();
    s  = sh[0] + sh[1] + sh[2] + sh[3];
    s2 = sh[4] + sh[5] + sh[6] + sh[7];
    float mean = s * (1.f / 128.f);
    float var  = s2 * (1.f / 128.f) - mean * mean;
    float x = (v - mean) * rsqrtf(var + 1e-5f) * lng[t] + lnb[t];
    sv[t] = fmaxf(x, 0.f);
    __syncthreads();
    int w = t >> 5, lane = t & 31;
    for (int hh = w; hh < 8; hh += 4) {
        const float* wr = &Wg2[hh * 128];
        float p = sv[lane] * wr[lane] + sv[lane + 32] * wr[lane + 32]
                + sv[lane + 64] * wr[lane + 64] + sv[lane + 96] * wr[lane + 96];
#pragma unroll
        for (int off = 16; off; off >>= 1) p += __shfl_xor_sync(0xFFFFFFFFu, p, off);
        if (lane == 0) logits[hh] = p + bg2[hh];
    }
    __syncthreads();
    if (t == 0) {
        float mx = -1e30f;
#pragma unroll
        for (int hh = 0; hh < 8; hh++) mx = fmaxf(mx, logits[hh]);
        float e[8], sum = 0.f;
#pragma unroll
        for (int hh = 0; hh < 8; hh++) { e[hh] = __expf(logits[hh] - mx); sum += e[hh]; }
        float isum = 1.f / sum;
#pragma unroll
        for (int hh = 0; hh < 8; hh++) gates[(size_t)row * 8 + hh] = e[hh] * isum;
    }
}

// ---------------- fused = sum_h cma[b, h*C + c, n] * gates[b,n,h] ----------
__global__ __launch_bounds__(256)
void fused_kernel(const float* __restrict__ cma, const float* __restrict__ gates,
                  float* __restrict__ out) {
    int idx = blockIdx.x * 256 + threadIdx.x;
    int n = idx & 511;
    int c = (idx >> 9) & 511;
    int b = idx >> 18;
    const float* gp = &gates[((size_t)b * 512 + n) * 8];
    const float* cp = &cma[(size_t)b * HC * NN + (size_t)c * NN + n];
    float acc = 0.f;
#pragma unroll
    for (int hh = 0; hh < 8; hh++)
        acc += cp[(size_t)hh * CC * NN] * gp[hh];
    out[idx] = acc;
}

// ---------------- host launcher --------------------------------------------
extern "C" void kernel_launch(void* const* d_in, const int* in_sizes, int n_in,
                              void* d_out, int out_size) {
    const float* q    = (const float*)d_in[0];
    const float* k    = (const float*)d_in[1];
    const float* v    = (const float*)d_in[2];
    const float* cma  = (const float*)d_in[3];
    const float* Wq   = (const float*)d_in[4];
    const float* bq   = (const float*)d_in[5];
    const float* Wk   = (const float*)d_in[6];
    const float* bk   = (const float*)d_in[7];
    const float* Wv   = (const float*)d_in[8];
    const float* bv   = (const float*)d_in[9];
    const float* Wo   = (const float*)d_in[10];
    const float* bo   = (const float*)d_in[11];
    const float* ln1g = (const float*)d_in[12];
    const float* ln1b = (const float*)d_in[13];
    const float* ln2g = (const float*)d_in[14];
    const float* ln2b = (const float*)d_in[15];
    const float* W1   = (const float*)d_in[16];
    const float* b1   = (const float*)d_in[17];
    const float* W2   = (const float*)d_in[18];
    const float* b2   = (const float*)d_in[19];
    const float* Wg1  = (const float*)d_in[20];
    const float* bg1  = (const float*)d_in[21];
    const float* lngg = (const float*)d_in[22];
    const float* lngb = (const float*)d_in[23];
    const float* Wg2  = (const float*)d_in[24];
    const float* bg2  = (const float*)d_in[25];

    float *p_qkv, *p_o, *p_x, *p_ff2, *p_ghr, *p_gates, *p_bqkv, *p_wg1;
    __half *p_att16, *p_x16, *p_ffh16, *p_q16, *p_k16, *p_v16;
    __half *p_wqkv16, *p_wo16, *p_w116, *p_w216;
    cudaGetSymbolAddress((void**)&p_qkv, g_qkv);
    cudaGetSymbolAddress((void**)&p_att16, g_att16);
    cudaGetSymbolAddress((void**)&p_o,   g_o);
    cudaGetSymbolAddress((void**)&p_x,   g_x);
    cudaGetSymbolAddress((void**)&p_x16, g_x16);
    cudaGetSymbolAddress((void**)&p_ffh16, g_ffh16);
    cudaGetSymbolAddress((void**)&p_ff2, g_ff2);
    cudaGetSymbolAddress((void**)&p_ghr, g_ghr);
    cudaGetSymbolAddress((void**)&p_gates, g_gates);
    cudaGetSymbolAddress((void**)&p_q16, g_q16);
    cudaGetSymbolAddress((void**)&p_k16, g_k16);
    cudaGetSymbolAddress((void**)&p_v16, g_v16);
    cudaGetSymbolAddress((void**)&p_wqkv16, g_wqkv16);
    cudaGetSymbolAddress((void**)&p_bqkv, g_bqkv);
    cudaGetSymbolAddress((void**)&p_wo16, g_wo16);
    cudaGetSymbolAddress((void**)&p_w116, g_w116);
    cudaGetSymbolAddress((void**)&p_w216, g_w216);
    cudaGetSymbolAddress((void**)&p_wg1, g_wg1);

    cudaFuncSetAttribute(flash_attn_kernel, cudaFuncAttributeMaxDynamicSharedMemorySize, FL_SMEM);
    cudaFuncSetAttribute(gemm_h<0,false,true>,  cudaFuncAttributeMaxDynamicSharedMemorySize, HSMEM);
    cudaFuncSetAttribute(gemm_h<0,false,false>, cudaFuncAttributeMaxDynamicSharedMemorySize, HSMEM);
    cudaFuncSetAttribute(gemm_h<1,true,false>,  cudaFuncAttributeMaxDynamicSharedMemorySize, HSMEM);
    cudaFuncSetAttribute(gemm_gate, cudaFuncAttributeMaxDynamicSharedMemorySize, GT_SMEM);

    float* out_enc   = (float*)d_out;                       // [B,N,D]
    float* out_fused = (float*)d_out + (size_t)MM * DD;     // [B,C,N]

    // weight / activation pre-conversion
    pack_qkv_w16_kernel<<<3*DD*DD/2048, 256>>>(Wq, Wk, Wv, p_wqkv16);
    pack_qkv_b_kernel<<<6, 256>>>(bq, bk, bv, p_bqkv);
    cvt_f16_kernel<<<DD*DD/2048, 256>>>(Wo, p_wo16, DD*DD);
    cvt_f16_kernel<<<DFF*DD/2048, 256>>>(W1, p_w116, DFF*DD);
    cvt_f16_kernel<<<DD*DFF/2048, 256>>>(W2, p_w216, DD*DFF);
    cvt_f16_kernel<<<MM*DD/2048, 256>>>(q, p_q16, MM*DD);
    cvt_f16_kernel<<<MM*DD/2048, 256>>>(k, p_k16, MM*DD);
    cvt_f16_kernel<<<MM*DD/2048, 256>>>(v, p_v16, MM*DD);
    cvt_tf32_kernel<<<GHH*HC/1024, 256>>>(Wg1, p_wg1, GHH*HC);

    // QKV projections (cross-attn: z selects q/k/v input), packed fp32 out
    gemm_h<0,false,true><<<dim3(MM/128, 4, 3), 256, HSMEM>>>(
        p_q16, p_wqkv16, p_bqkv, p_qkv, MM, DD, 1536, p_k16, p_v16);
    // flash attention (fp32 in, fp16 out)
    flash_attn_kernel<<<dim3(BB*HH, NN/64), 128, FL_SMEM>>>(p_qkv, p_att16);
    // output projection + LN1 (fp32 + fp16 x)
    gemm_h<0,false,false><<<dim3(MM/128, DD/128), 256, HSMEM>>>(
        p_att16, p_wo16, bo, p_o, MM, DD, DD, nullptr, nullptr);
    add_ln_kernel<<<MM, 128>>>(q, p_o, ln1g, ln1b, p_x, p_x16);
    // FFN (fp16 in/out for the hidden, fp32 final)
    gemm_h<1,true,false><<<dim3(MM/128, DFF/128), 256, HSMEM>>>(
        p_x16, p_w116, b1, p_ffh16, MM, DD, DFF, nullptr, nullptr);
    gemm_h<0,false,false><<<dim3(MM/128, DD/128), 256, HSMEM>>>(
        p_ffh16, p_w216, b2, p_ff2, MM, DFF, DD, nullptr, nullptr);
    add_ln_kernel<<<MM, 128>>>(p_x, p_ff2, ln2g, ln2b, out_enc, nullptr);
    // gate MLP (tf32, strided A from cma) + finisher
    gemm_gate<<<MM/128, 256, GT_SMEM>>>(cma, p_wg1, bg1, p_ghr);
    gate_finish_kernel<<<MM, 128>>>(p_ghr, lngg, lngb, Wg2, bg2, p_gates);
    // gated fusion
    fused_kernel<<<(BB*CC*NN)/256, 256>>>(cma, p_gates, out_fused);
}

// round 16
// speedup vs baseline: 3.8647x; 1.0294x over previous
#include <cuda_runtime.h>
#include <cuda_fp16.h>
#include <cstdint>
#include <cmath>

// Problem constants
#define BB 16
#define NN 512
#define DD 512
#define HH 8
#define DKK 64
#define DFF 2048
#define GHH 128
#define MM (BB*NN)          // 8192
#define HC (HH*DD)          // 4096
#define CC 512              // HC / H

// ---------------- scratch (device globals; no allocation allowed) ----------
__device__ float  g_qkv [MM*3*DD];    // packed QKV (fp32, read by flash)
__device__ __half g_att16[MM*DD];     // attention out (fp16, feeds Wo)
__device__ float  g_o   [MM*DD];
__device__ float  g_x   [MM*DD];
__device__ __half g_x16 [MM*DD];      // fp16 copy of x (feeds FFN1)
__device__ __half g_ffh16[MM*DFF];    // GELU out (fp16, feeds FFN2)
__device__ float  g_ff2 [MM*DD];
__device__ float  g_ghr [MM*GHH];
__device__ float  g_gates[MM*HH];
// fp16 activations of inputs
__device__ __half g_q16 [MM*DD];
__device__ __half g_k16 [MM*DD];
__device__ __half g_v16 [MM*DD];
// pre-converted weights
__device__ __half g_wqkv16[3*DD*DD];  // [1536][512] rows: Wq|Wk|Wv (fp16)
__device__ float  g_bqkv[3*DD];
__device__ __half g_wo16[DD*DD];
__device__ __half g_w116[DFF*DD];
__device__ __half g_w216[DD*DFF];
__device__ float  g_wg1 [GHH*HC];     // tf32-rounded (gate GEMM stays tf32)

__device__ __forceinline__ uint32_t f2tf32(float x) {
    uint32_t r;
    asm("cvt.rna.tf32.f32 %0, %1;" : "=r"(r) : "f"(x));
    return r;
}
__device__ __forceinline__ void mma8(float* d, uint32_t a0, uint32_t a1,
                                     uint32_t a2, uint32_t a3,
                                     uint32_t b0, uint32_t b1) {
    asm volatile("mma.sync.aligned.m16n8k8.row.col.f32.tf32.tf32.f32 "
        "{%0,%1,%2,%3}, {%4,%5,%6,%7}, {%8,%9}, {%0,%1,%2,%3};"
        : "+f"(d[0]), "+f"(d[1]), "+f"(d[2]), "+f"(d[3])
        : "r"(a0), "r"(a1), "r"(a2), "r"(a3), "r"(b0), "r"(b1));
}
__device__ __forceinline__ void mma16(float* d, uint32_t a0, uint32_t a1,
                                      uint32_t a2, uint32_t a3,
                                      uint32_t b0, uint32_t b1) {
    asm volatile("mma.sync.aligned.m16n8k16.row.col.f32.f16.f16.f32 "
        "{%0,%1,%2,%3}, {%4,%5,%6,%7}, {%8,%9}, {%0,%1,%2,%3};"
        : "+f"(d[0]), "+f"(d[1]), "+f"(d[2]), "+f"(d[3])
        : "r"(a0), "r"(a1), "r"(a2), "r"(a3), "r"(b0), "r"(b1));
}
__device__ __forceinline__ void ldmx4(uint32_t* r, uint32_t addr) {
    asm volatile("ldmatrix.sync.aligned.m8n8.x4.shared.b16 {%0,%1,%2,%3}, [%4];"
        : "=r"(r[0]), "=r"(r[1]), "=r"(r[2]), "=r"(r[3]) : "r"(addr));
}
__device__ __forceinline__ uint32_t smem_u32(const void* p) {
    return (uint32_t)__cvta_generic_to_shared(p);
}
__device__ __forceinline__ void cp16(uint32_t dst, const void* src) {
    asm volatile("cp.async.cg.shared.global [%0], [%1], 16;" :: "r"(dst), "l"(src));
}

// ---------------- weight / activation pre-conversion -----------------------
__global__ __launch_bounds__(256)
void cvt_tf32_kernel(const float* __restrict__ src, float* __restrict__ dst, int n) {
    int i = (blockIdx.x * 256 + threadIdx.x) * 4;
    if (i < n) {
        float4 v = *(const float4*)&src[i];
        uint4 u = {f2tf32(v.x), f2tf32(v.y), f2tf32(v.z), f2tf32(v.w)};
        *(uint4*)&dst[i] = u;
    }
}
__global__ __launch_bounds__(256)
void cvt_f16_kernel(const float* __restrict__ src, __half* __restrict__ dst, int n) {
    int i = (blockIdx.x * 256 + threadIdx.x) * 8;
    if (i < n) {
        float4 a = *(const float4*)&src[i];
        float4 b = *(const float4*)&src[i + 4];
        __half2 h0 = __floats2half2_rn(a.x, a.y);
        __half2 h1 = __floats2half2_rn(a.z, a.w);
        __half2 h2 = __floats2half2_rn(b.x, b.y);
        __half2 h3 = __floats2half2_rn(b.z, b.w);
        uint4 u = {*(uint32_t*)&h0, *(uint32_t*)&h1, *(uint32_t*)&h2, *(uint32_t*)&h3};
        *(uint4*)&dst[i] = u;
    }
}
__global__ __launch_bounds__(256)
void pack_qkv_w16_kernel(const float* __restrict__ Wq, const float* __restrict__ Wk,
                         const float* __restrict__ Wv, __half* __restrict__ dst) {
    int i = (blockIdx.x * 256 + threadIdx.x) * 8;   // over 1536*512
    int row = i >> 9, col = i & 511;
    const float* src = (row < 512) ? &Wq[(size_t)row * 512 + col]
                     : (row < 1024) ? &Wk[(size_t)(row - 512) * 512 + col]
                                    : &Wv[(size_t)(row - 1024) * 512 + col];
    float4 a = *(const float4*)&src[0];
    float4 b = *(const float4*)&src[4];
    __half2 h0 = __floats2half2_rn(a.x, a.y);
    __half2 h1 = __floats2half2_rn(a.z, a.w);
    __half2 h2 = __floats2half2_rn(b.x, b.y);
    __half2 h3 = __floats2half2_rn(b.z, b.w);
    uint4 u = {*(uint32_t*)&h0, *(uint32_t*)&h1, *(uint32_t*)&h2, *(uint32_t*)&h3};
    *(uint4*)&dst[i] = u;
}
__global__ __launch_bounds__(256)
void pack_qkv_b_kernel(const float* __restrict__ bq, const float* __restrict__ bk,
                       const float* __restrict__ bv, float* __restrict__ dst) {
    int i = blockIdx.x * 256 + threadIdx.x;
    dst[i] = (i < 512) ? bq[i] : (i < 1024) ? bk[i - 512] : bv[i - 1024];
}

// ================= fp16 mma.sync GEMM: C = A @ W^T + bias =================
// CTA 128x128, chunk = 32 halves, 3-stage cp.async, 256 thr = 8 warps (4Mx2N).
// Fragment loads via ldmatrix.x4 (12 per warp-chunk vs 48 LDS.32).
// FUSE3: blockIdx.z picks A from {A,A1,A2}, n0 += z*512 (packed QKV).
#define HA_STG32 (2 * 128 * 20)   // A+B stage size in u32
#define HSMEM (3 * HA_STG32 * 4)  // 61440 B

__device__ __forceinline__ void issue_stage_h(
    const __half* __restrict__ A, const __half* __restrict__ W,
    int K, int m0, int n0, int k0, int t, uint32_t sA, uint32_t sB) {
#pragma unroll
    for (int p = 0; p < 2; p++) {
        int idx = p * 256 + t;
        int row = idx >> 2, f = idx & 3;
        cp16(sA + (uint32_t)(row * 80 + f * 16),
             &A[(size_t)(m0 + row) * K + k0 + f * 8]);
        cp16(sB + (uint32_t)(row * 80 + f * 16),
             &W[(size_t)(n0 + row) * K + k0 + f * 8]);
    }
    asm volatile("cp.async.commit_group;" ::: "memory");
}

template<int EPI, bool OUT16, bool FUSE3>
__global__ __launch_bounds__(256, 2)
void gemm_h(const __half* __restrict__ A, const __half* __restrict__ W,
            const float* __restrict__ bias, void* __restrict__ Cv,
            int M, int K, int Nn,
            const __half* __restrict__ A1, const __half* __restrict__ A2) {
    extern __shared__ uint32_t hsm[];
    const uint32_t sbase = smem_u32(hsm);
    const int t = threadIdx.x;
    const int lane = t & 31, wid = t >> 5;
    const int wm = (wid >> 1) * 32;
    const int wn = (wid & 1) * 64;
    const int m0 = blockIdx.x * 128;
    int n0 = blockIdx.y * 128;
    const __half* Ax = A;
    if (FUSE3) {
        const int z = blockIdx.z;
        Ax = (z == 0) ? A : (z == 1) ? A1 : A2;
        n0 += z * 512;
    }
    const int g = lane >> 2, c = lane & 3;
    // ldmatrix per-lane address components
    const int tq = lane >> 3, tr = lane & 7;
    const int arow = tr + ((tq & 1) << 3);     // A: q0/q1 rows, q2/q3 koff+4
    const int akoff = (tq >> 1) << 2;
    const int brow = tr + ((tq >> 1) << 3);    // B: q0/q1 koff, q2/q3 rows+8
    const int bkoff = (tq & 1) << 2;
    const int NSTEP = K / 32;

    float acc[2][8][4];
#pragma unroll
    for (int im = 0; im < 2; im++)
#pragma unroll
        for (int jn = 0; jn < 8; jn++)
#pragma unroll
            for (int e = 0; e < 4; e++) acc[im][jn][e] = 0.f;

    issue_stage_h(Ax, W, K, m0, n0, 0,  t, sbase, sbase + 128 * 80);
    issue_stage_h(Ax, W, K, m0, n0, 32, t, sbase + HA_STG32 * 4, sbase + HA_STG32 * 4 + 128 * 80);

    for (int s = 0; s < NSTEP; s++) {
        if (s == NSTEP - 1)
            asm volatile("cp.async.wait_group 0;" ::: "memory");
        else
            asm volatile("cp.async.wait_group 1;" ::: "memory");
        __syncthreads();
        if (s + 2 < NSTEP) {
            int st = (s + 2) % 3;
            issue_stage_h(Ax, W, K, m0, n0, (s + 2) * 32, t,
                          sbase + (uint32_t)(st * HA_STG32) * 4,
                          sbase + (uint32_t)(st * HA_STG32) * 4 + 128 * 80);
        }
        const uint32_t aB = sbase + (uint32_t)((s % 3) * HA_STG32) * 4;
        const uint32_t bB = aB + 128 * 80;
#pragma unroll
        for (int kk8 = 0; kk8 < 16; kk8 += 8) {          // 2 x k16 steps
            uint32_t af[2][4];
            ldmx4(af[0], aB + (uint32_t)((wm + arow) * 20 + kk8 + akoff) * 4);
            ldmx4(af[1], aB + (uint32_t)((wm + 16 + arow) * 20 + kk8 + akoff) * 4);
#pragma unroll
            for (int jp = 0; jp < 4; jp++) {
                uint32_t bf[4];
                ldmx4(bf, bB + (uint32_t)((wn + jp * 16 + brow) * 20 + kk8 + bkoff) * 4);
#pragma unroll
                for (int im = 0; im < 2; im++) {
                    mma16(acc[im][jp * 2],     af[im][0], af[im][1], af[im][2], af[im][3], bf[0], bf[1]);
                    mma16(acc[im][jp * 2 + 1], af[im][0], af[im][1], af[im][2], af[im][3], bf[2], bf[3]);
                }
            }
        }
        __syncthreads();
    }
    // ---- epilogue ----
#pragma unroll
    for (int jn = 0; jn < 8; jn++) {
        int col = n0 + wn + jn * 8 + 2 * c;
        float bv0 = bias[col], bv1 = bias[col + 1];
#pragma unroll
        for (int im = 0; im < 2; im++) {
            int row = m0 + wm + im * 16 + g;
            float v00 = acc[im][jn][0] + bv0;
            float v01 = acc[im][jn][1] + bv1;
            float v10 = acc[im][jn][2] + bv0;
            float v11 = acc[im][jn][3] + bv1;
            if (EPI == 1) {
                v00 = 0.5f * v00 * (1.f + erff(v00 * 0.70710678118654752f));
                v01 = 0.5f * v01 * (1.f + erff(v01 * 0.70710678118654752f));
                v10 = 0.5f * v10 * (1.f + erff(v10 * 0.70710678118654752f));
                v11 = 0.5f * v11 * (1.f + erff(v11 * 0.70710678118654752f));
            }
            if (OUT16) {
                __half* C = (__half*)Cv;
                __half2 h0 = __floats2half2_rn(v00, v01);
                __half2 h1 = __floats2half2_rn(v10, v11);
                *(__half2*)&C[(size_t)row * Nn + col] = h0;
                *(__half2*)&C[(size_t)(row + 8) * Nn + col] = h1;
            } else {
                float* C = (float*)Cv;
                float2 r0 = {v00, v01}, r1 = {v10, v11};
                *(float2*)&C[(size_t)row * Nn + col] = r0;
                *(float2*)&C[(size_t)(row + 8) * Nn + col] = r1;
            }
        }
    }
}

// ================= tf32 GEMM for the gate MLP (strided A from cma) =========
#define GT_ASZ (32 * 132)
#define GT_BSZ (128 * 36)
#define GT_STG (GT_ASZ + GT_BSZ)
#define GT_SMEM (3 * GT_STG * 4)

__device__ __forceinline__ void issue_stage_g(
    const float* __restrict__ A, const float* __restrict__ W,
    int m0, int k0, int t, uint32_t sA, uint32_t sB) {
    const int b = m0 >> 9, nb = m0 & 511;
#pragma unroll
    for (int p = 0; p < 4; p++) {
        int idx = p * 256 + t;
        int kc = idx >> 5, nf = idx & 31;
        cp16(sA + (uint32_t)(kc * 132 + nf * 4) * 4,
             &A[(size_t)b * HC * 512 + (size_t)(k0 + kc) * 512 + nb + nf * 4]);
    }
#pragma unroll
    for (int p = 0; p < 4; p++) {
        int idx = p * 256 + t;
        int row = idx >> 3, f4 = idx & 7;
        cp16(sB + (uint32_t)(row * 36 + f4 * 4) * 4,
             &W[(size_t)row * HC + k0 + f4 * 4]);
    }
    asm volatile("cp.async.commit_group;" ::: "memory");
}

__global__ __launch_bounds__(256, 2)
void gemm_gate(const float* __restrict__ A, const float* __restrict__ W,
               const float* __restrict__ bias, float* __restrict__ C) {
    extern __shared__ float gsm[];
    const uint32_t sbase = smem_u32(gsm);
    const int t = threadIdx.x;
    const int lane = t & 31, wid = t >> 5;
    const int wm = (wid >> 1) * 32;
    const int wn = (wid & 1) * 64;
    const int m0 = blockIdx.x * 128;
    const int g = lane >> 2, c = lane & 3;
    const int NSTEP = HC / 32;

    float acc[2][8][4];
#pragma unroll
    for (int im = 0; im < 2; im++)
#pragma unroll
        for (int jn = 0; jn < 8; jn++)
#pragma unroll
            for (int e = 0; e < 4; e++) acc[im][jn][e] = 0.f;

    issue_stage_g(A, W, m0, 0,  t, sbase, sbase + GT_ASZ * 4);
    issue_stage_g(A, W, m0, 32, t, sbase + GT_STG * 4, sbase + (GT_STG + GT_ASZ) * 4);

    for (int s = 0; s < NSTEP; s++) {
        if (s == NSTEP - 1)
            asm volatile("cp.async.wait_group 0;" ::: "memory");
        else
            asm volatile("cp.async.wait_group 1;" ::: "memory");
        __syncthreads();
        if (s + 2 < NSTEP) {
            int st = (s + 2) % 3;
            issue_stage_g(A, W, m0, (s + 2) * 32, t,
                          sbase + (uint32_t)(st * GT_STG) * 4,
                          sbase + (uint32_t)(st * GT_STG + GT_ASZ) * 4);
        }
        const uint32_t* As = (const uint32_t*)(gsm + (s % 3) * GT_STG);
        const uint32_t* Bs = As + GT_ASZ;
#pragma unroll
        for (int ks = 0; ks < 4; ks++) {
            const int k8 = ks * 8;
            uint32_t af[2][4];
#pragma unroll
            for (int im = 0; im < 2; im++) {
                const int m = wm + im * 16;
                af[im][0] = f2tf32(__uint_as_float(As[(k8 + c) * 132 + m + g]));
                af[im][1] = f2tf32(__uint_as_float(As[(k8 + c) * 132 + m + g + 8]));
                af[im][2] = f2tf32(__uint_as_float(As[(k8 + c + 4) * 132 + m + g]));
                af[im][3] = f2tf32(__uint_as_float(As[(k8 + c + 4) * 132 + m + g + 8]));
            }
#pragma unroll
            for (int jn = 0; jn < 8; jn++) {
                const int n = wn + jn * 8;
                uint32_t b0 = Bs[(n + g) * 36 + k8 + c];
                uint32_t b1 = Bs[(n + g) * 36 + k8 + c + 4];
#pragma unroll
                for (int im = 0; im < 2; im++)
                    mma8(acc[im][jn], af[im][0], af[im][1], af[im][2], af[im][3], b0, b1);
            }
        }
        __syncthreads();
    }
#pragma unroll
    for (int jn = 0; jn < 8; jn++) {
        int col = wn + jn * 8 + 2 * c;
        float bv0 = bias[col], bv1 = bias[col + 1];
#pragma unroll
        for (int im = 0; im < 2; im++) {
            int row = m0 + wm + im * 16 + g;
            float2 r0 = {acc[im][jn][0] + bv0, acc[im][jn][1] + bv1};
            float2 r1 = {acc[im][jn][2] + bv0, acc[im][jn][3] + bv1};
            *(float2*)&C[(size_t)row * GHH + col] = r0;
            *(float2*)&C[(size_t)(row + 8) * GHH + col] = r1;
        }
    }
}

// ================= flash attention (online softmax, tf32 mma) ==============
#define FL_SMEM ((64*68*3 + 64*72) * 4)

__global__ __launch_bounds__(128)
void flash_attn_kernel(const float* __restrict__ QKV, __half* __restrict__ O16) {
    extern __shared__ uint32_t fsm[];
    uint32_t* Qs = fsm;              // [64][68]
    uint32_t* Ks = Qs + 64 * 68;     // [64][68]
    uint32_t* Ps = Ks + 64 * 68;     // [64][68]
    uint32_t* Vs = Ps + 64 * 68;     // [64][72]

    const int bh = blockIdx.x;
    const int b = bh >> 3, h = bh & 7;
    const int q0 = blockIdx.y * 64;
    const int t = threadIdx.x;
    const int lane = t & 31, wid = t >> 5;
    const int g = lane >> 2, c = lane & 3;
    const int wm = wid * 16;
    const size_t qb = (size_t)b * NN * 1536 + h * 64;
    const float sc = 0.125f;

#pragma unroll
    for (int p = 0; p < 8; p++) {
        int idx = p * 128 + t;
        int r = idx >> 4, f4 = (idx & 15) * 4;
        float4 v = *(const float4*)&QKV[qb + (size_t)(q0 + r) * 1536 + f4];
        uint4 u = {f2tf32(v.x), f2tf32(v.y), f2tf32(v.z), f2tf32(v.w)};
        *(uint4*)&Qs[r * 68 + f4] = u;
    }

    float o[8][4];
#pragma unroll
    for (int nt = 0; nt < 8; nt++)
#pragma unroll
        for (int e = 0; e < 4; e++) o[nt][e] = 0.f;
    float M0 = -1e30f, M1 = -1e30f, l0 = 0.f, l1 = 0.f;

    for (int c0 = 0; c0 < NN; c0 += 64) {
        __syncthreads();
#pragma unroll
        for (int p = 0; p < 8; p++) {
            int idx = p * 128 + t;
            int r = idx >> 4, f4 = (idx & 15) * 4;
            float4 kv = *(const float4*)&QKV[qb + 512 + (size_t)(c0 + r) * 1536 + f4];
            uint4 uk = {f2tf32(kv.x), f2tf32(kv.y), f2tf32(kv.z), f2tf32(kv.w)};
            *(uint4*)&Ks[r * 68 + f4] = uk;
            float4 vv = *(const float4*)&QKV[qb + 1024 + (size_t)(c0 + r) * 1536 + f4];
            uint4 uv = {f2tf32(vv.x), f2tf32(vv.y), f2tf32(vv.z), f2tf32(vv.w)};
            *(uint4*)&Vs[r * 72 + f4] = uv;
        }
        __syncthreads();

        float s[8][4];
#pragma unroll
        for (int nt = 0; nt < 8; nt++)
#pragma unroll
            for (int e = 0; e < 4; e++) s[nt][e] = 0.f;
#pragma unroll
        for (int k8 = 0; k8 < 8; k8++) {
            uint32_t a0 = Qs[(wm + g) * 68 + k8 * 8 + c];
            uint32_t a1 = Qs[(wm + g + 8) * 68 + k8 * 8 + c];
            uint32_t a2 = Qs[(wm + g) * 68 + k8 * 8 + c + 4];
            uint32_t a3 = Qs[(wm + g + 8) * 68 + k8 * 8 + c + 4];
#pragma unroll
            for (int nt = 0; nt < 8; nt++) {
                uint32_t b0 = Ks[(nt * 8 + g) * 68 + k8 * 8 + c];
                uint32_t b1 = Ks[(nt * 8 + g) * 68 + k8 * 8 + c + 4];
                mma8(s[nt], a0, a1, a2, a3, b0, b1);
            }
        }

        float mx0 = -1e30f, mx1 = -1e30f;
#pragma unroll
        for (int nt = 0; nt < 8; nt++) {
            mx0 = fmaxf(mx0, fmaxf(s[nt][0], s[nt][1]));
            mx1 = fmaxf(mx1, fmaxf(s[nt][2], s[nt][3]));
        }
        mx0 *= sc; mx1 *= sc;
        mx0 = fmaxf(mx0, __shfl_xor_sync(0xFFFFFFFFu, mx0, 1));
        mx0 = fmaxf(mx0, __shfl_xor_sync(0xFFFFFFFFu, mx0, 2));
        mx1 = fmaxf(mx1, __shfl_xor_sync(0xFFFFFFFFu, mx1, 1));
        mx1 = fmaxf(mx1, __shfl_xor_sync(0xFFFFFFFFu, mx1, 2));
        float Mn0 = fmaxf(M0, mx0), Mn1 = fmaxf(M1, mx1);
        float es0 = __expf(M0 - Mn0), es1 = __expf(M1 - Mn1);
        M0 = Mn0; M1 = Mn1;
        float sum0 = 0.f, sum1 = 0.f;
#pragma unroll
        for (int nt = 0; nt < 8; nt++) {
            float p00 = __expf(sc * s[nt][0] - Mn0);
            float p01 = __expf(sc * s[nt][1] - Mn0);
            float p10 = __expf(sc * s[nt][2] - Mn1);
            float p11 = __expf(sc * s[nt][3] - Mn1);
            sum0 += p00 + p01; sum1 += p10 + p11;
            uint2 w0 = {f2tf32(p00), f2tf32(p01)};
            uint2 w1 = {f2tf32(p10), f2tf32(p11)};
            *(uint2*)&Ps[(wm + g) * 68 + nt * 8 + 2 * c] = w0;
            *(uint2*)&Ps[(wm + g + 8) * 68 + nt * 8 + 2 * c] = w1;
        }
        l0 = l0 * es0 + sum0;
        l1 = l1 * es1 + sum1;
#pragma unroll
        for (int nt = 0; nt < 8; nt++) {
            o[nt][0] *= es0; o[nt][1] *= es0;
            o[nt][2] *= es1; o[nt][3] *= es1;
        }
        __syncwarp();

#pragma unroll
        for (int k8 = 0; k8 < 8; k8++) {
            uint32_t a0 = Ps[(wm + g) * 68 + k8 * 8 + c];
            uint32_t a1 = Ps[(wm + g + 8) * 68 + k8 * 8 + c];
            uint32_t a2 = Ps[(wm + g) * 68 + k8 * 8 + c + 4];
            uint32_t a3 = Ps[(wm + g + 8) * 68 + k8 * 8 + c + 4];
#pragma unroll
            for (int nt = 0; nt < 8; nt++) {
                uint32_t b0 = Vs[(k8 * 8 + c) * 72 + nt * 8 + g];
                uint32_t b1 = Vs[(k8 * 8 + c + 4) * 72 + nt * 8 + g];
                mma8(o[nt], a0, a1, a2, a3, b0, b1);
            }
        }
    }

    l0 += __shfl_xor_sync(0xFFFFFFFFu, l0, 1);
    l0 += __shfl_xor_sync(0xFFFFFFFFu, l0, 2);
    l1 += __shfl_xor_sync(0xFFFFFFFFu, l1, 1);
    l1 += __shfl_xor_sync(0xFFFFFFFFu, l1, 2);
    float iv0 = 1.f / l0, iv1 = 1.f / l1;
    const size_t ob = ((size_t)b * NN) * DD + h * DKK;
#pragma unroll
    for (int nt = 0; nt < 8; nt++) {
        int col = nt * 8 + 2 * c;
        __half2 r0 = __floats2half2_rn(o[nt][0] * iv0, o[nt][1] * iv0);
        __half2 r1 = __floats2half2_rn(o[nt][2] * iv1, o[nt][3] * iv1);
        *(__half2*)&O16[ob + (size_t)(q0 + wm + g) * DD + col] = r0;
        *(__half2*)&O16[ob + (size_t)(q0 + wm + g + 8) * DD + col] = r1;
    }
}

// ---------------- residual + LayerNorm (optional fp16 copy) ----------------
__global__ __launch_bounds__(128)
void add_ln_kernel(const float* __restrict__ X, const float* __restrict__ Y,
                   const float* __restrict__ g, const float* __restrict__ bt,
                   float* __restrict__ out, __half* __restrict__ out16) {
    __shared__ float sh[8];
    const int row = blockIdx.x;
    const int t = threadIdx.x;
    float4 x4 = *(const float4*)&X[(size_t)row * 512 + t * 4];
    float4 y4 = *(const float4*)&Y[(size_t)row * 512 + t * 4];
    float v[4] = {x4.x + y4.x, x4.y + y4.y, x4.z + y4.z, x4.w + y4.w};
    float s = v[0] + v[1] + v[2] + v[3];
    float s2 = v[0]*v[0] + v[1]*v[1] + v[2]*v[2] + v[3]*v[3];
#pragma unroll
    for (int off = 16; off; off >>= 1) {
        s  += __shfl_xor_sync(0xFFFFFFFFu, s, off);
        s2 += __shfl_xor_sync(0xFFFFFFFFu, s2, off);
    }
    if ((t & 31) == 0) { sh[t >> 5] = s; sh[4 + (t >> 5)] = s2; }
    __syncthreads();
    s  = sh[0] + sh[1] + sh[2] + sh[3];
    s2 = sh[4] + sh[5] + sh[6] + sh[7];
    float mean = s * (1.f / 512.f);
    float var  = s2 * (1.f / 512.f) - mean * mean;
    float rs = rsqrtf(var + 1e-5f);
    float4 g4 = *(const float4*)&g[t * 4];
    float4 b4 = *(const float4*)&bt[t * 4];
    float4 r;
    r.x = (v[0] - mean) * rs * g4.x + b4.x;
    r.y = (v[1] - mean) * rs * g4.y + b4.y;
    r.z = (v[2] - mean) * rs * g4.z + b4.z;
    r.w = (v[3] - mean) * rs * g4.w + b4.w;
    *(float4*)&out[(size_t)row * 512 + t * 4] = r;
    if (out16) {
        __half2 h0 = __floats2half2_rn(r.x, r.y);
        __half2 h1 = __floats2half2_rn(r.z, r.w);
        *(__half2*)&out16[(size_t)row * 512 + t * 4] = h0;
        *(__half2*)&out16[(size_t)row * 512 + t * 4 + 2] = h1;
    }
}

// ---------------- gate finisher: LN(128) -> ReLU -> Linear(128,8) -> softmax
__global__ __launch_bounds__(128)
void gate_finish_kernel(const float* __restrict__ Hraw,
                        const float* __restrict__ lng, const float* __restrict__ lnb,
                        const float* __restrict__ Wg2, const float* __restrict__ bg2,
                        float* __restrict__ gates) {
    __shared__ float sh[8];
    __shared__ float sv[128];
    __shared__ float logits[8];
    const int row = blockIdx.x;
    const int t = threadIdx.x;
    float v = Hraw[(size_t)row * 128 + t];
    float s = v, s2 = v * v;
#pragma unroll
    for (int off = 16; off; off >>= 1) {
        s  += __shfl_xor_sync(0xFFFFFFFFu, s, off);
        s2 += __shfl_xor_sync(0xFFFFFFFFu, s2, off);
    }
    if ((t & 31) == 0) { sh[t >> 5] = s; sh[4 + (t >> 5)] = s2; }
    __syncthreads();
    s  = sh[0] + sh[1] + sh[2] + sh[3];
    s2 = sh[4] + sh[5] + sh[6] + sh[7];
    float mean = s * (1.f / 128.f);
    float var  = s2 * (1.f / 128.f) - mean * mean;
    float x = (v - mean) * rsqrtf(var + 1e-5f) * lng[t] + lnb[t];
    sv[t] = fmaxf(x, 0.f);
    __syncthreads();
    int w = t >> 5, lane = t & 31;
    for (int hh = w; hh < 8; hh += 4) {
        const float* wr = &Wg2[hh * 128];
        float p = sv[lane] * wr[lane] + sv[lane + 32] * wr[lane + 32]
                + sv[lane + 64] * wr[lane + 64] + sv[lane + 96] * wr[lane + 96];
#pragma unroll
        for (int off = 16; off; off >>= 1) p += __shfl_xor_sync(0xFFFFFFFFu, p, off);
        if (lane == 0) logits[hh] = p + bg2[hh];
    }
    __syncthreads();
    if (t == 0) {
        float mx = -1e30f;
#pragma unroll
        for (int hh = 0; hh < 8; hh++) mx = fmaxf(mx, logits[hh]);
        float e[8], sum = 0.f;
#pragma unroll
        for (int hh = 0; hh < 8; hh++) { e[hh] = __expf(logits[hh] - mx); sum += e[hh]; }
        float isum = 1.f / sum;
#pragma unroll
        for (int hh = 0; hh < 8; hh++) gates[(size_t)row * 8 + hh] = e[hh] * isum;
    }
}

// ---------------- fused = sum_h cma[b, h*C + c, n] * gates[b,n,h] ----------
__global__ __launch_bounds__(256)
void fused_kernel(const float* __restrict__ cma, const float* __restrict__ gates,
                  float* __restrict__ out) {
    int idx = blockIdx.x * 256 + threadIdx.x;
    int n = idx & 511;
    int c = (idx >> 9) & 511;
    int b = idx >> 18;
    const float* gp = &gates[((size_t)b * 512 + n) * 8];
    const float* cp = &cma[(size_t)b * HC * NN + (size_t)c * NN + n];
    float acc = 0.f;
#pragma unroll
    for (int hh = 0; hh < 8; hh++)
        acc += cp[(size_t)hh * CC * NN] * gp[hh];
    out[idx] = acc;
}

// ---------------- host launcher --------------------------------------------
extern "C" void kernel_launch(void* const* d_in, const int* in_sizes, int n_in,
                              void* d_out, int out_size) {
    const float* q    = (const float*)d_in[0];
    const float* k    = (const float*)d_in[1];
    const float* v    = (const float*)d_in[2];
    const float* cma  = (const float*)d_in[3];
    const float* Wq   = (const float*)d_in[4];
    const float* bq   = (const float*)d_in[5];
    const float* Wk   = (const float*)d_in[6];
    const float* bk   = (const float*)d_in[7];
    const float* Wv   = (const float*)d_in[8];
    const float* bv   = (const float*)d_in[9];
    const float* Wo   = (const float*)d_in[10];
    const float* bo   = (const float*)d_in[11];
    const float* ln1g = (const float*)d_in[12];
    const float* ln1b = (const float*)d_in[13];
    const float* ln2g = (const float*)d_in[14];
    const float* ln2b = (const float*)d_in[15];
    const float* W1   = (const float*)d_in[16];
    const float* b1   = (const float*)d_in[17];
    const float* W2   = (const float*)d_in[18];
    const float* b2   = (const float*)d_in[19];
    const float* Wg1  = (const float*)d_in[20];
    const float* bg1  = (const float*)d_in[21];
    const float* lngg = (const float*)d_in[22];
    const float* lngb = (const float*)d_in[23];
    const float* Wg2  = (const float*)d_in[24];
    const float* bg2  = (const float*)d_in[25];

    float *p_qkv, *p_o, *p_x, *p_ff2, *p_ghr, *p_gates, *p_bqkv, *p_wg1;
    __half *p_att16, *p_x16, *p_ffh16, *p_q16, *p_k16, *p_v16;
    __half *p_wqkv16, *p_wo16, *p_w116, *p_w216;
    cudaGetSymbolAddress((void**)&p_qkv, g_qkv);
    cudaGetSymbolAddress((void**)&p_att16, g_att16);
    cudaGetSymbolAddress((void**)&p_o,   g_o);
    cudaGetSymbolAddress((void**)&p_x,   g_x);
    cudaGetSymbolAddress((void**)&p_x16, g_x16);
    cudaGetSymbolAddress((void**)&p_ffh16, g_ffh16);
    cudaGetSymbolAddress((void**)&p_ff2, g_ff2);
    cudaGetSymbolAddress((void**)&p_ghr, g_ghr);
    cudaGetSymbolAddress((void**)&p_gates, g_gates);
    cudaGetSymbolAddress((void**)&p_q16, g_q16);
    cudaGetSymbolAddress((void**)&p_k16, g_k16);
    cudaGetSymbolAddress((void**)&p_v16, g_v16);
    cudaGetSymbolAddress((void**)&p_wqkv16, g_wqkv16);
    cudaGetSymbolAddress((void**)&p_bqkv, g_bqkv);
    cudaGetSymbolAddress((void**)&p_wo16, g_wo16);
    cudaGetSymbolAddress((void**)&p_w116, g_w116);
    cudaGetSymbolAddress((void**)&p_w216, g_w216);
    cudaGetSymbolAddress((void**)&p_wg1, g_wg1);

    cudaFuncSetAttribute(flash_attn_kernel, cudaFuncAttributeMaxDynamicSharedMemorySize, FL_SMEM);
    cudaFuncSetAttribute(gemm_h<0,false,true>,  cudaFuncAttributeMaxDynamicSharedMemorySize, HSMEM);
    cudaFuncSetAttribute(gemm_h<0,false,false>, cudaFuncAttributeMaxDynamicSharedMemorySize, HSMEM);
    cudaFuncSetAttribute(gemm_h<1,true,false>,  cudaFuncAttributeMaxDynamicSharedMemorySize, HSMEM);
    cudaFuncSetAttribute(gemm_gate, cudaFuncAttributeMaxDynamicSharedMemorySize, GT_SMEM);

    float* out_enc   = (float*)d_out;                       // [B,N,D]
    float* out_fused = (float*)d_out + (size_t)MM * DD;     // [B,C,N]

    // weight / activation pre-conversion
    pack_qkv_w16_kernel<<<3*DD*DD/2048, 256>>>(Wq, Wk, Wv, p_wqkv16);
    pack_qkv_b_kernel<<<6, 256>>>(bq, bk, bv, p_bqkv);
    cvt_f16_kernel<<<DD*DD/2048, 256>>>(Wo, p_wo16, DD*DD);
    cvt_f16_kernel<<<DFF*DD/2048, 256>>>(W1, p_w116, DFF*DD);
    cvt_f16_kernel<<<DD*DFF/2048, 256>>>(W2, p_w216, DD*DFF);
    cvt_f16_kernel<<<MM*DD/2048, 256>>>(q, p_q16, MM*DD);
    cvt_f16_kernel<<<MM*DD/2048, 256>>>(k, p_k16, MM*DD);
    cvt_f16_kernel<<<MM*DD/2048, 256>>>(v, p_v16, MM*DD);
    cvt_tf32_kernel<<<GHH*HC/1024, 256>>>(Wg1, p_wg1, GHH*HC);

    // QKV projections (cross-attn: z selects q/k/v input), packed fp32 out
    gemm_h<0,false,true><<<dim3(MM/128, 4, 3), 256, HSMEM>>>(
        p_q16, p_wqkv16, p_bqkv, p_qkv, MM, DD, 1536, p_k16, p_v16);
    // flash attention (fp32 in, fp16 out)
    flash_attn_kernel<<<dim3(BB*HH, NN/64), 128, FL_SMEM>>>(p_qkv, p_att16);
    // output projection + LN1 (fp32 + fp16 x)
    gemm_h<0,false,false><<<dim3(MM/128, DD/128), 256, HSMEM>>>(
        p_att16, p_wo16, bo, p_o, MM, DD, DD, nullptr, nullptr);
    add_ln_kernel<<<MM, 128>>>(q, p_o, ln1g, ln1b, p_x, p_x16);
    // FFN (fp16 in/out for the hidden, fp32 final)
    gemm_h<1,true,false><<<dim3(MM/128, DFF/128), 256, HSMEM>>>(
        p_x16, p_w116, b1, p_ffh16, MM, DD, DFF, nullptr, nullptr);
    gemm_h<0,false,false><<<dim3(MM/128, DD/128), 256, HSMEM>>>(
        p_ffh16, p_w216, b2, p_ff2, MM, DFF, DD, nullptr, nullptr);
    add_ln_kernel<<<MM, 128>>>(p_x, p_ff2, ln2g, ln2b, out_enc, nullptr);
    // gate MLP (tf32, strided A from cma) + finisher
    gemm_gate<<<MM/128, 256, GT_SMEM>>>(cma, p_wg1, bg1, p_ghr);
    gate_finish_kernel<<<MM, 128>>>(p_ghr, lngg, lngb, Wg2, bg2, p_gates);
    // gated fusion
    fused_kernel<<<(BB*CC*NN)/256, 256>>>(cma, p_gates, out_fused);
}